// round 14
// baseline (speedup 1.0000x reference)
#include <cuda_runtime.h>
#include <math.h>
#include <stdint.h>

#define LTOK 4800
#define TTOK 9600
#define CDIM 256
#define KSEL 16
#define NLAYER 8
#define SIM_SCALE (1.0f/25.6f)

// ------------------------- device scratch ---------------------------------
__device__ float g_simA[(size_t)LTOK * LTOK];
__device__ float g_simB[(size_t)LTOK * LTOK];
__device__ float g_koff00[LTOK];
__device__ float g_koff11[LTOK];
__device__ float g_koffA[LTOK];
__device__ float g_koffB[LTOK];
__device__ int   g_idx00[LTOK * KSEL];
__device__ int   g_idx11[LTOK * KSEL];
__device__ int   g_idx01[LTOK * KSEL];
__device__ int   g_idx10[LTOK * KSEL];
__device__ float g_F[TTOK * CDIM];
__device__ float g_X[TTOK * CDIM];
// layer-major: [layer][token][256]
__device__ float g_KEall[(size_t)NLAYER * TTOK * CDIM];
__device__ float g_Vall[(size_t)NLAYER * TTOK * CDIM];
__device__ float g_Qb[TTOK * CDIM];
__device__ float g_attn[TTOK * CDIM];
__device__ float g_msg[TTOK * CDIM];
__device__ float g_cat[TTOK * 2 * CDIM];
__device__ float g_h1[TTOK * 2 * CDIM];
__device__ float g_y[TTOK * CDIM];

__device__ __forceinline__ uint32_t f2tf(float f)
{
    uint32_t r;
    asm("cvt.rna.tf32.f32 %0, %1;" : "=r"(r) : "f"(f));
    return r;
}
__device__ __forceinline__ void split2(float v, uint32_t& h, uint32_t& l)
{
    h = f2tf(v);
    l = f2tf(v - __uint_as_float(h));
}

#define MMA_TF32(acc, a0,a1,a2,a3, b0,b1) \
    asm volatile("mma.sync.aligned.m16n8k8.row.col.f32.tf32.tf32.f32 " \
        "{%0,%1,%2,%3}, {%4,%5,%6,%7}, {%8,%9}, {%0,%1,%2,%3};\n" \
        : "+f"(acc[0]), "+f"(acc[1]), "+f"(acc[2]), "+f"(acc[3]) \
        : "r"(a0), "r"(a1), "r"(a2), "r"(a3), "r"(b0), "r"(b1))

// ======== split-tf32 sim GEMM: C = scale * (A @ B^T), fp32-accurate ========
template <int SYM>
__global__ void __launch_bounds__(256, 2)
gemm_nt_tc(const float* __restrict__ A, const float* __restrict__ B,
           float* __restrict__ C, float* __restrict__ CT, float scale)
{
    if (SYM && blockIdx.y > blockIdx.x) return;

    __shared__ uint32_t Ah[128][20], Al[128][20], Bh[128][20], Bl[128][20];

    const int tid  = threadIdx.x;
    const int lane = tid & 31;
    const int warp = tid >> 5;
    const int wm   = warp & 3;
    const int wn   = warp >> 2;
    const int bm   = blockIdx.y * 128;
    const int bn   = blockIdx.x * 128;
    const int g    = lane >> 2;
    const int t4   = lane & 3;

    float acc[2][8][4];
    #pragma unroll
    for (int mt = 0; mt < 2; mt++)
        #pragma unroll
        for (int nt = 0; nt < 8; nt++)
            #pragma unroll
            for (int r = 0; r < 4; r++) acc[mt][nt][r] = 0.f;

    const int rr = tid >> 2;
    const int rk = (tid & 3) * 4;

    float4 pa[2], pb[2];

    #pragma unroll
    for (int j = 0; j < 2; j++) {
        int ra = min(bm + rr + 64 * j, LTOK - 1);
        int rb = min(bn + rr + 64 * j, LTOK - 1);
        pa[j] = *(const float4*)(A + (size_t)ra * CDIM + rk);
        pb[j] = *(const float4*)(B + (size_t)rb * CDIM + rk);
    }
    #pragma unroll
    for (int j = 0; j < 2; j++) {
        int r = rr + 64 * j;
        split2(pa[j].x, Ah[r][rk+0], Al[r][rk+0]);
        split2(pa[j].y, Ah[r][rk+1], Al[r][rk+1]);
        split2(pa[j].z, Ah[r][rk+2], Al[r][rk+2]);
        split2(pa[j].w, Ah[r][rk+3], Al[r][rk+3]);
        split2(pb[j].x, Bh[r][rk+0], Bl[r][rk+0]);
        split2(pb[j].y, Bh[r][rk+1], Bl[r][rk+1]);
        split2(pb[j].z, Bh[r][rk+2], Bl[r][rk+2]);
        split2(pb[j].w, Bh[r][rk+3], Bl[r][rk+3]);
    }
    __syncthreads();

    const int NT = CDIM / 16;
    for (int kt = 0; kt < NT; kt++) {
        if (kt + 1 < NT) {
            const int k0 = (kt + 1) << 4;
            #pragma unroll
            for (int j = 0; j < 2; j++) {
                int ra = min(bm + rr + 64 * j, LTOK - 1);
                int rb = min(bn + rr + 64 * j, LTOK - 1);
                pa[j] = *(const float4*)(A + (size_t)ra * CDIM + k0 + rk);
                pb[j] = *(const float4*)(B + (size_t)rb * CDIM + k0 + rk);
            }
        }

        #pragma unroll
        for (int ks = 0; ks < 16; ks += 8) {
            uint32_t ah[2][4], al[2][4];
            #pragma unroll
            for (int mt = 0; mt < 2; mt++) {
                int mrow = wm * 32 + mt * 16 + g;
                ah[mt][0] = Ah[mrow    ][ks + t4    ];
                ah[mt][1] = Ah[mrow + 8][ks + t4    ];
                ah[mt][2] = Ah[mrow    ][ks + t4 + 4];
                ah[mt][3] = Ah[mrow + 8][ks + t4 + 4];
                al[mt][0] = Al[mrow    ][ks + t4    ];
                al[mt][1] = Al[mrow + 8][ks + t4    ];
                al[mt][2] = Al[mrow    ][ks + t4 + 4];
                al[mt][3] = Al[mrow + 8][ks + t4 + 4];
            }
            uint32_t bh[8][2], bl[8][2];
            #pragma unroll
            for (int nt = 0; nt < 8; nt++) {
                int ncol = wn * 64 + nt * 8 + g;
                bh[nt][0] = Bh[ncol][ks + t4    ];
                bh[nt][1] = Bh[ncol][ks + t4 + 4];
                bl[nt][0] = Bl[ncol][ks + t4    ];
                bl[nt][1] = Bl[ncol][ks + t4 + 4];
            }
            #pragma unroll
            for (int mt = 0; mt < 2; mt++)
                #pragma unroll
                for (int nt = 0; nt < 8; nt++) {
                    MMA_TF32(acc[mt][nt], ah[mt][0], ah[mt][1], ah[mt][2], ah[mt][3],
                             bl[nt][0], bl[nt][1]);
                    MMA_TF32(acc[mt][nt], al[mt][0], al[mt][1], al[mt][2], al[mt][3],
                             bh[nt][0], bh[nt][1]);
                    MMA_TF32(acc[mt][nt], ah[mt][0], ah[mt][1], ah[mt][2], ah[mt][3],
                             bh[nt][0], bh[nt][1]);
                }
        }
        __syncthreads();

        if (kt + 1 < NT) {
            #pragma unroll
            for (int j = 0; j < 2; j++) {
                int r = rr + 64 * j;
                split2(pa[j].x, Ah[r][rk+0], Al[r][rk+0]);
                split2(pa[j].y, Ah[r][rk+1], Al[r][rk+1]);
                split2(pa[j].z, Ah[r][rk+2], Al[r][rk+2]);
                split2(pa[j].w, Ah[r][rk+3], Al[r][rk+3]);
                split2(pb[j].x, Bh[r][rk+0], Bl[r][rk+0]);
                split2(pb[j].y, Bh[r][rk+1], Bl[r][rk+1]);
                split2(pb[j].z, Bh[r][rk+2], Bl[r][rk+2]);
                split2(pb[j].w, Bh[r][rk+3], Bl[r][rk+3]);
            }
            __syncthreads();
        }
    }

    float* Cmir = SYM ? C : CT;
    const bool offdiag = !SYM || (blockIdx.y != blockIdx.x);
    #pragma unroll
    for (int mt = 0; mt < 2; mt++) {
        #pragma unroll
        for (int nt = 0; nt < 8; nt++) {
            int row0 = bm + wm * 32 + mt * 16 + g;
            int col  = bn + wn * 64 + nt * 8 + 2 * t4;
            float v0 = acc[mt][nt][0] * scale, v1 = acc[mt][nt][1] * scale;
            float v2 = acc[mt][nt][2] * scale, v3 = acc[mt][nt][3] * scale;
            if (col < LTOK) {
                if (row0 < LTOK)
                    *(float2*)(C + (size_t)row0 * LTOK + col) = make_float2(v0, v1);
                if (row0 + 8 < LTOK)
                    *(float2*)(C + (size_t)(row0 + 8) * LTOK + col) = make_float2(v2, v3);
            }
            if (offdiag || !SYM) {
                if (row0 < LTOK) {
                    if (col < LTOK)     Cmir[(size_t)col * LTOK + row0]       = v0;
                    if (col + 1 < LTOK) Cmir[(size_t)(col + 1) * LTOK + row0] = v1;
                }
                if (row0 + 8 < LTOK) {
                    if (col < LTOK)     Cmir[(size_t)col * LTOK + row0 + 8]       = v2;
                    if (col + 1 < LTOK) Cmir[(size_t)(col + 1) * LTOK + row0 + 8] = v3;
                }
            } else if (SYM) {
                if (row0 < LTOK) {
                    if (col < LTOK)     C[(size_t)col * LTOK + row0]       = v0;
                    if (col + 1 < LTOK) C[(size_t)(col + 1) * LTOK + row0] = v1;
                }
                if (row0 + 8 < LTOK) {
                    if (col < LTOK)     C[(size_t)col * LTOK + row0 + 8]       = v2;
                    if (col + 1 < LTOK) C[(size_t)(col + 1) * LTOK + row0 + 8] = v3;
                }
            }
        }
    }
}

// ====== tf32 GEMM, 128x128 tile (KV stacked) — single-sync double buffer ===
template <int ACT, int STACKB>
__global__ void __launch_bounds__(256, 2)
gemm128(const float* __restrict__ A, const float* __restrict__ B,
        float* __restrict__ C, int M, int N, int Kd)
{
    __shared__ uint32_t As[2][128][20];
    __shared__ uint32_t Bs[2][16][136];

    const int tid  = threadIdx.x;
    const int lane = tid & 31;
    const int warp = tid >> 5;
    const int wm   = warp & 3;
    const int wn   = warp >> 2;
    const int bm   = blockIdx.y * 128;
    const int bn   = blockIdx.x * 128;
    const int g  = lane >> 2;
    const int t4 = lane & 3;

    float acc[2][8][4];
    #pragma unroll
    for (int mt = 0; mt < 2; mt++)
        #pragma unroll
        for (int nt = 0; nt < 8; nt++)
            #pragma unroll
            for (int r = 0; r < 4; r++) acc[mt][nt][r] = 0.f;

    const int ar = tid >> 2;
    const int ak = (tid & 3) * 4;
    const int brow = tid >> 5;
    const int bcol = (tid & 31) * 4;

    const float* bptr;
    size_t bstride;
    if (STACKB) {
        int ncol = bn + bcol;
        bptr = B + (size_t)(ncol >> 8) * (CDIM * CDIM) + (ncol & 255);
        bstride = CDIM;
    } else {
        bptr = B + bn + bcol;
        bstride = (size_t)N;
    }

    const int NT = Kd >> 4;
    float4 pa[2], pb[2];

    #pragma unroll
    for (int j = 0; j < 2; j++) {
        pa[j] = *(const float4*)(A + (size_t)(bm + ar + 64 * j) * Kd + ak);
        pb[j] = *(const float4*)(bptr + (size_t)(brow + 8 * j) * bstride);
    }
    #pragma unroll
    for (int j = 0; j < 2; j++) {
        As[0][ar + 64 * j][ak + 0] = f2tf(pa[j].x);
        As[0][ar + 64 * j][ak + 1] = f2tf(pa[j].y);
        As[0][ar + 64 * j][ak + 2] = f2tf(pa[j].z);
        As[0][ar + 64 * j][ak + 3] = f2tf(pa[j].w);
        Bs[0][brow + 8 * j][bcol + 0] = f2tf(pb[j].x);
        Bs[0][brow + 8 * j][bcol + 1] = f2tf(pb[j].y);
        Bs[0][brow + 8 * j][bcol + 2] = f2tf(pb[j].z);
        Bs[0][brow + 8 * j][bcol + 3] = f2tf(pb[j].w);
    }
    __syncthreads();

    int buf = 0;
    for (int kt = 0; kt < NT; kt++) {
        if (kt + 1 < NT) {
            const int k0 = (kt + 1) << 4;
            #pragma unroll
            for (int j = 0; j < 2; j++) {
                pa[j] = *(const float4*)(A + (size_t)(bm + ar + 64 * j) * Kd + k0 + ak);
                pb[j] = *(const float4*)(bptr + (size_t)(k0 + brow + 8 * j) * bstride);
            }
        }

        #pragma unroll
        for (int ks = 0; ks < 16; ks += 8) {
            uint32_t af[2][4];
            #pragma unroll
            for (int mt = 0; mt < 2; mt++) {
                int mrow = wm * 32 + mt * 16 + g;
                af[mt][0] = As[buf][mrow    ][ks + t4    ];
                af[mt][1] = As[buf][mrow + 8][ks + t4    ];
                af[mt][2] = As[buf][mrow    ][ks + t4 + 4];
                af[mt][3] = As[buf][mrow + 8][ks + t4 + 4];
            }
            uint32_t bf[8][2];
            #pragma unroll
            for (int nt = 0; nt < 8; nt++) {
                int ncol = wn * 64 + nt * 8 + g;
                bf[nt][0] = Bs[buf][ks + t4    ][ncol];
                bf[nt][1] = Bs[buf][ks + t4 + 4][ncol];
            }
            #pragma unroll
            for (int mt = 0; mt < 2; mt++)
                #pragma unroll
                for (int nt = 0; nt < 8; nt++)
                    MMA_TF32(acc[mt][nt], af[mt][0], af[mt][1], af[mt][2], af[mt][3],
                             bf[nt][0], bf[nt][1]);
        }

        if (kt + 1 < NT) {
            int nb = buf ^ 1;
            #pragma unroll
            for (int j = 0; j < 2; j++) {
                As[nb][ar + 64 * j][ak + 0] = f2tf(pa[j].x);
                As[nb][ar + 64 * j][ak + 1] = f2tf(pa[j].y);
                As[nb][ar + 64 * j][ak + 2] = f2tf(pa[j].z);
                As[nb][ar + 64 * j][ak + 3] = f2tf(pa[j].w);
                Bs[nb][brow + 8 * j][bcol + 0] = f2tf(pb[j].x);
                Bs[nb][brow + 8 * j][bcol + 1] = f2tf(pb[j].y);
                Bs[nb][brow + 8 * j][bcol + 2] = f2tf(pb[j].z);
                Bs[nb][brow + 8 * j][bcol + 3] = f2tf(pb[j].w);
            }
            __syncthreads();
            buf = nb;
        }
    }

    #pragma unroll
    for (int mt = 0; mt < 2; mt++) {
        #pragma unroll
        for (int nt = 0; nt < 8; nt++) {
            int row = bm + wm * 32 + mt * 16 + g;
            int col = bn + wn * 64 + nt * 8 + 2 * t4;
            float v0 = acc[mt][nt][0], v1 = acc[mt][nt][1];
            float v2 = acc[mt][nt][2], v3 = acc[mt][nt][3];
            if (ACT == 1) {
                v0 = (v0 > 0.f) ? v0 + 1.f : expf(v0);
                v1 = (v1 > 0.f) ? v1 + 1.f : expf(v1);
                v2 = (v2 > 0.f) ? v2 + 1.f : expf(v2);
                v3 = (v3 > 0.f) ? v3 + 1.f : expf(v3);
            } else if (ACT == 2) {
                v0 = fmaxf(v0, 0.f); v1 = fmaxf(v1, 0.f);
                v2 = fmaxf(v2, 0.f); v3 = fmaxf(v3, 0.f);
            }
            if (STACKB) {
                size_t base = (size_t)(col >> 8) * ((size_t)TTOK * CDIM) + (col & 255);
                *(float2*)(C + base + (size_t)row * CDIM)       = make_float2(v0, v1);
                *(float2*)(C + base + (size_t)(row + 8) * CDIM) = make_float2(v2, v3);
            } else {
                *(float2*)(C + (size_t)row * N + col)       = make_float2(v0, v1);
                *(float2*)(C + (size_t)(row + 8) * N + col) = make_float2(v2, v3);
            }
        }
    }
}

// ====== tf32 GEMM, 128x64 tile — single-sync double buffer (W1) ============
template <int ACT>
__global__ void __launch_bounds__(256, 2)
gemm64(const float* __restrict__ A, const float* __restrict__ B,
       float* __restrict__ C, int M, int N, int Kd)
{
    __shared__ uint32_t As[2][128][20];
    __shared__ uint32_t Bs[2][16][72];

    const int tid  = threadIdx.x;
    const int lane = tid & 31;
    const int warp = tid >> 5;
    const int wm   = warp & 3;
    const int wn   = warp >> 2;
    const int bm   = blockIdx.y * 128;
    const int bn   = blockIdx.x * 64;
    const int g  = lane >> 2;
    const int t4 = lane & 3;

    float acc[2][4][4];
    #pragma unroll
    for (int mt = 0; mt < 2; mt++)
        #pragma unroll
        for (int nt = 0; nt < 4; nt++)
            #pragma unroll
            for (int r = 0; r < 4; r++) acc[mt][nt][r] = 0.f;

    const int ar = tid >> 2;
    const int ak = (tid & 3) * 4;
    const int brow = tid >> 4;
    const int bcol = (tid & 15) * 4;

    const int NT = Kd >> 4;
    float4 pa[2], pb;

    #pragma unroll
    for (int j = 0; j < 2; j++)
        pa[j] = *(const float4*)(A + (size_t)(bm + ar + 64 * j) * Kd + ak);
    pb = *(const float4*)(B + (size_t)brow * N + bn + bcol);
    #pragma unroll
    for (int j = 0; j < 2; j++) {
        As[0][ar + 64 * j][ak + 0] = f2tf(pa[j].x);
        As[0][ar + 64 * j][ak + 1] = f2tf(pa[j].y);
        As[0][ar + 64 * j][ak + 2] = f2tf(pa[j].z);
        As[0][ar + 64 * j][ak + 3] = f2tf(pa[j].w);
    }
    Bs[0][brow][bcol + 0] = f2tf(pb.x);
    Bs[0][brow][bcol + 1] = f2tf(pb.y);
    Bs[0][brow][bcol + 2] = f2tf(pb.z);
    Bs[0][brow][bcol + 3] = f2tf(pb.w);
    __syncthreads();

    int buf = 0;
    for (int kt = 0; kt < NT; kt++) {
        if (kt + 1 < NT) {
            const int k0 = (kt + 1) << 4;
            #pragma unroll
            for (int j = 0; j < 2; j++)
                pa[j] = *(const float4*)(A + (size_t)(bm + ar + 64 * j) * Kd + k0 + ak);
            pb = *(const float4*)(B + (size_t)(k0 + brow) * N + bn + bcol);
        }

        #pragma unroll
        for (int ks = 0; ks < 16; ks += 8) {
            uint32_t af[2][4];
            #pragma unroll
            for (int mt = 0; mt < 2; mt++) {
                int mrow = wm * 32 + mt * 16 + g;
                af[mt][0] = As[buf][mrow    ][ks + t4    ];
                af[mt][1] = As[buf][mrow + 8][ks + t4    ];
                af[mt][2] = As[buf][mrow    ][ks + t4 + 4];
                af[mt][3] = As[buf][mrow + 8][ks + t4 + 4];
            }
            uint32_t bf[4][2];
            #pragma unroll
            for (int nt = 0; nt < 4; nt++) {
                int ncol = wn * 32 + nt * 8 + g;
                bf[nt][0] = Bs[buf][ks + t4    ][ncol];
                bf[nt][1] = Bs[buf][ks + t4 + 4][ncol];
            }
            #pragma unroll
            for (int mt = 0; mt < 2; mt++)
                #pragma unroll
                for (int nt = 0; nt < 4; nt++)
                    MMA_TF32(acc[mt][nt], af[mt][0], af[mt][1], af[mt][2], af[mt][3],
                             bf[nt][0], bf[nt][1]);
        }

        if (kt + 1 < NT) {
            int nb = buf ^ 1;
            #pragma unroll
            for (int j = 0; j < 2; j++) {
                As[nb][ar + 64 * j][ak + 0] = f2tf(pa[j].x);
                As[nb][ar + 64 * j][ak + 1] = f2tf(pa[j].y);
                As[nb][ar + 64 * j][ak + 2] = f2tf(pa[j].z);
                As[nb][ar + 64 * j][ak + 3] = f2tf(pa[j].w);
            }
            Bs[nb][brow][bcol + 0] = f2tf(pb.x);
            Bs[nb][brow][bcol + 1] = f2tf(pb.y);
            Bs[nb][brow][bcol + 2] = f2tf(pb.z);
            Bs[nb][brow][bcol + 3] = f2tf(pb.w);
            __syncthreads();
            buf = nb;
        }
    }

    #pragma unroll
    for (int mt = 0; mt < 2; mt++) {
        #pragma unroll
        for (int nt = 0; nt < 4; nt++) {
            int row = bm + wm * 32 + mt * 16 + g;
            int col = bn + wn * 32 + nt * 8 + 2 * t4;
            float v0 = acc[mt][nt][0], v1 = acc[mt][nt][1];
            float v2 = acc[mt][nt][2], v3 = acc[mt][nt][3];
            if (ACT == 1) {
                v0 = (v0 > 0.f) ? v0 + 1.f : expf(v0);
                v1 = (v1 > 0.f) ? v1 + 1.f : expf(v1);
                v2 = (v2 > 0.f) ? v2 + 1.f : expf(v2);
                v3 = (v3 > 0.f) ? v3 + 1.f : expf(v3);
            } else if (ACT == 2) {
                v0 = fmaxf(v0, 0.f); v1 = fmaxf(v1, 0.f);
                v2 = fmaxf(v2, 0.f); v3 = fmaxf(v3, 0.f);
            }
            *(float2*)(C + (size_t)row * N + col)       = make_float2(v0, v1);
            *(float2*)(C + (size_t)(row + 8) * N + col) = make_float2(v2, v3);
        }
    }
}

// ====== tf32 GEMM, 64x64 tile — wave-balanced, 3 CTAs/SM (Q/Wm/W2) =========
// 256 threads, 8 warps as 2x4: warp tile 32x16 = 2x2 m16n8k8.
// smem 19.4KB/CTA, acc 16 regs -> fits 3 CTAs/SM (85-reg cap, no spill).
// Grid 600 CTAs on 444 slots -> 1.35 waves; 24 warps/SM hide LDS latency.
template <int ACT>
__global__ void __launch_bounds__(256, 3)
gemm6464(const float* __restrict__ A, const float* __restrict__ B,
         float* __restrict__ C, int M, int N, int Kd)
{
    __shared__ uint32_t As[2][64][20];
    __shared__ uint32_t Bs[2][16][72];

    const int tid  = threadIdx.x;
    const int lane = tid & 31;
    const int warp = tid >> 5;
    const int wm   = warp & 1;            // 2 m-blocks of 32
    const int wn   = warp >> 1;           // 4 n-blocks of 16
    const int bm   = blockIdx.y * 64;
    const int bn   = blockIdx.x * 64;
    const int g  = lane >> 2;
    const int t4 = lane & 3;

    float acc[2][2][4];
    #pragma unroll
    for (int mt = 0; mt < 2; mt++)
        #pragma unroll
        for (int nt = 0; nt < 2; nt++)
            #pragma unroll
            for (int r = 0; r < 4; r++) acc[mt][nt][r] = 0.f;

    const int ar = tid >> 2;              // 0..63
    const int ak = (tid & 3) * 4;
    const int brow = tid >> 4;            // 0..15
    const int bcol = (tid & 15) * 4;

    const int NT = Kd >> 4;
    float4 pa, pb;

    pa = *(const float4*)(A + (size_t)(bm + ar) * Kd + ak);
    pb = *(const float4*)(B + (size_t)brow * N + bn + bcol);
    As[0][ar][ak + 0] = f2tf(pa.x);
    As[0][ar][ak + 1] = f2tf(pa.y);
    As[0][ar][ak + 2] = f2tf(pa.z);
    As[0][ar][ak + 3] = f2tf(pa.w);
    Bs[0][brow][bcol + 0] = f2tf(pb.x);
    Bs[0][brow][bcol + 1] = f2tf(pb.y);
    Bs[0][brow][bcol + 2] = f2tf(pb.z);
    Bs[0][brow][bcol + 3] = f2tf(pb.w);
    __syncthreads();

    int buf = 0;
    for (int kt = 0; kt < NT; kt++) {
        if (kt + 1 < NT) {
            const int k0 = (kt + 1) << 4;
            pa = *(const float4*)(A + (size_t)(bm + ar) * Kd + k0 + ak);
            pb = *(const float4*)(B + (size_t)(k0 + brow) * N + bn + bcol);
        }

        #pragma unroll
        for (int ks = 0; ks < 16; ks += 8) {
            uint32_t af[2][4];
            #pragma unroll
            for (int mt = 0; mt < 2; mt++) {
                int mrow = wm * 32 + mt * 16 + g;
                af[mt][0] = As[buf][mrow    ][ks + t4    ];
                af[mt][1] = As[buf][mrow + 8][ks + t4    ];
                af[mt][2] = As[buf][mrow    ][ks + t4 + 4];
                af[mt][3] = As[buf][mrow + 8][ks + t4 + 4];
            }
            uint32_t bf[2][2];
            #pragma unroll
            for (int nt = 0; nt < 2; nt++) {
                int ncol = wn * 16 + nt * 8 + g;
                bf[nt][0] = Bs[buf][ks + t4    ][ncol];
                bf[nt][1] = Bs[buf][ks + t4 + 4][ncol];
            }
            #pragma unroll
            for (int mt = 0; mt < 2; mt++)
                #pragma unroll
                for (int nt = 0; nt < 2; nt++)
                    MMA_TF32(acc[mt][nt], af[mt][0], af[mt][1], af[mt][2], af[mt][3],
                             bf[nt][0], bf[nt][1]);
        }

        if (kt + 1 < NT) {
            int nb = buf ^ 1;
            As[nb][ar][ak + 0] = f2tf(pa.x);
            As[nb][ar][ak + 1] = f2tf(pa.y);
            As[nb][ar][ak + 2] = f2tf(pa.z);
            As[nb][ar][ak + 3] = f2tf(pa.w);
            Bs[nb][brow][bcol + 0] = f2tf(pb.x);
            Bs[nb][brow][bcol + 1] = f2tf(pb.y);
            Bs[nb][brow][bcol + 2] = f2tf(pb.z);
            Bs[nb][brow][bcol + 3] = f2tf(pb.w);
            __syncthreads();
            buf = nb;
        }
    }

    #pragma unroll
    for (int mt = 0; mt < 2; mt++) {
        #pragma unroll
        for (int nt = 0; nt < 2; nt++) {
            int row = bm + wm * 32 + mt * 16 + g;
            int col = bn + wn * 16 + nt * 8 + 2 * t4;
            float v0 = acc[mt][nt][0], v1 = acc[mt][nt][1];
            float v2 = acc[mt][nt][2], v3 = acc[mt][nt][3];
            if (ACT == 1) {
                v0 = (v0 > 0.f) ? v0 + 1.f : expf(v0);
                v1 = (v1 > 0.f) ? v1 + 1.f : expf(v1);
                v2 = (v2 > 0.f) ? v2 + 1.f : expf(v2);
                v3 = (v3 > 0.f) ? v3 + 1.f : expf(v3);
            } else if (ACT == 2) {
                v0 = fmaxf(v0, 0.f); v1 = fmaxf(v1, 0.f);
                v2 = fmaxf(v2, 0.f); v3 = fmaxf(v3, 0.f);
            }
            *(float2*)(C + (size_t)row * N + col)       = make_float2(v0, v1);
            *(float2*)(C + (size_t)(row + 8) * N + col) = make_float2(v2, v3);
        }
    }
}

// --------------- per-row logsumexp key offset (single pass) ----------------
__global__ void __launch_bounds__(256)
row_stats(const float* __restrict__ S, float* __restrict__ koff)
{
    const int row = blockIdx.x;
    const float* r = S + (size_t)row * LTOK;
    const int tid = threadIdx.x;
    __shared__ float sm[8], ss[8];

    float m = -1e30f, s = 0.f;
    for (int j = tid; j < LTOK; j += 256) {
        float x = r[j];
        if (x > m) { s = s * expf(m - x) + 1.f; m = x; }
        else       { s += expf(x - m); }
    }
    #pragma unroll
    for (int o = 16; o; o >>= 1) {
        float om = __shfl_down_sync(0xffffffffu, m, o);
        float os = __shfl_down_sync(0xffffffffu, s, o);
        float M = fmaxf(m, om);
        s = s * expf(m - M) + os * expf(om - M);
        m = M;
    }
    if ((tid & 31) == 0) { sm[tid >> 5] = m; ss[tid >> 5] = s; }
    __syncthreads();
    if (tid < 32) {
        float mm = (tid < 8) ? sm[tid] : -1e30f;
        float sv = (tid < 8) ? ss[tid] : 0.f;
        #pragma unroll
        for (int o = 4; o; o >>= 1) {
            float om = __shfl_down_sync(0xffffffffu, mm, o);
            float os = __shfl_down_sync(0xffffffffu, sv, o);
            float M = fmaxf(mm, om);
            sv = sv * expf(mm - M) + os * expf(om - M);
            mm = M;
        }
        if (tid == 0) koff[row] = mm + logf(sv);
    }
}

// -------------- top-16 per row (float4-vectorized scan) --------------------
__global__ void __launch_bounds__(256)
topk16(const float* __restrict__ S, const float* __restrict__ koff,
       int* __restrict__ out)
{
    const int row = blockIdx.x;
    const int tid = threadIdx.x;
    float lv[KSEL];
    int   li[KSEL];
    #pragma unroll
    for (int s = 0; s < KSEL; s++) { lv[s] = -1e30f; li[s] = 0x7fffffff; }

    const float4* r4 = (const float4*)(S + (size_t)row * LTOK);
    const float4* k4 = (const float4*)koff;
    const int NJ4 = LTOK / 4;   // 1200
    for (int j4 = tid; j4 < NJ4; j4 += 256) {
        const float4 rv4 = r4[j4];
        const float4 kv4 = k4[j4];
        float cand[4] = {2.f * rv4.x - kv4.x, 2.f * rv4.y - kv4.y,
                         2.f * rv4.z - kv4.z, 2.f * rv4.w - kv4.w};
        #pragma unroll
        for (int c = 0; c < 4; c++) {
            float nv = cand[c];
            int ni = j4 * 4 + c;
            if (nv > lv[KSEL - 1] || (nv == lv[KSEL - 1] && ni < li[KSEL - 1])) {
                #pragma unroll
                for (int s = 0; s < KSEL; s++) {
                    bool better = (nv > lv[s]) || (nv == lv[s] && ni < li[s]);
                    if (better) {
                        float tv = lv[s]; int ti = li[s];
                        lv[s] = nv; li[s] = ni; nv = tv; ni = ti;
                    }
                }
            }
        }
    }

    __shared__ float tv[256 * KSEL];
    __shared__ int   ti[256 * KSEL];
    __shared__ float rv[256];
    __shared__ int   ri[256];
    __shared__ int   rt[256];
    #pragma unroll
    for (int s = 0; s < KSEL; s++) { tv[tid * KSEL + s] = lv[s]; ti[tid * KSEL + s] = li[s]; }
    __syncthreads();

    int hp = 0;
    for (int k = 0; k < KSEL; k++) {
        rv[tid] = (hp < KSEL) ? tv[tid * KSEL + hp] : -1e30f;
        ri[tid] = (hp < KSEL) ? ti[tid * KSEL + hp] : 0x7fffffff;
        rt[tid] = tid;
        __syncthreads();
        for (int o = 128; o; o >>= 1) {
            if (tid < o) {
                float ov = rv[tid + o]; int oi = ri[tid + o];
                if (ov > rv[tid] || (ov == rv[tid] && oi < ri[tid])) {
                    rv[tid] = ov; ri[tid] = oi; rt[tid] = rt[tid + o];
                }
            }
            __syncthreads();
        }
        if (tid == 0) out[row * KSEL + k] = ri[0];
        if (tid == rt[0]) hp++;
        __syncthreads();
    }
}

// ---- linear attention: warp per token, shfl-only, float4 (no smem/bars) ---
__global__ void __launch_bounds__(256)
attn_w(const float* __restrict__ Q,
       const float* __restrict__ KE, const float* __restrict__ V,
       const int* __restrict__ idxA, const int* __restrict__ idxB,
       int srcOffA, int srcOffB,
       float* __restrict__ out)
{
    const int warp = threadIdx.x >> 5, lane = threadIdx.x & 31;
    const int t = blockIdx.x * 8 + warp;
    const int side = (t >= LTOK);
    const int tl = side ? t - LTOK : t;
    const int* idx = side ? idxB : idxA;
    const int srcOff = side ? srcOffB : srcOffA;

    int myidx = 0;
    if (lane < KSEL) myidx = srcOff + idx[tl * KSEL + lane];

    const float4* Q4  = (const float4*)Q;
    const float4* KE4 = (const float4*)KE;
    const float4* V4  = (const float4*)V;

    const float4 q0 = Q4[(size_t)t * 64 + lane * 2];
    const float4 q1 = Q4[(size_t)t * 64 + lane * 2 + 1];

    float o0x=0.f,o0y=0.f,o0z=0.f,o0w=0.f, o1x=0.f,o1y=0.f,o1z=0.f,o1w=0.f;
    float zs = 1e-6f;

    #pragma unroll
    for (int s = 0; s < KSEL; s++) {
        const int src = __shfl_sync(0xffffffffu, myidx, s);
        const size_t base = (size_t)src * 64 + lane * 2;
        const float4 k0 = KE4[base];
        const float4 k1 = KE4[base + 1];
        float p = q0.x*k0.x + q0.y*k0.y + q0.z*k0.z + q0.w*k0.w
                + q1.x*k1.x + q1.y*k1.y + q1.z*k1.z + q1.w*k1.w;
        p += __shfl_down_sync(0xffffffffu, p, 2);
        p += __shfl_down_sync(0xffffffffu, p, 1);
        const float sc = __shfl_sync(0xffffffffu, p, lane & 28);
        zs += sc;
        const float4 v0 = V4[base];
        const float4 v1 = V4[base + 1];
        o0x += sc * v0.x; o0y += sc * v0.y; o0z += sc * v0.z; o0w += sc * v0.w;
        o1x += sc * v1.x; o1y += sc * v1.y; o1z += sc * v1.z; o1w += sc * v1.w;
    }

    const float inv = 1.f / zs;
    float4* O4 = (float4*)out;
    O4[(size_t)t * 64 + lane * 2]     = make_float4(o0x*inv, o0y*inv, o0z*inv, o0w*inv);
    O4[(size_t)t * 64 + lane * 2 + 1] = make_float4(o1x*inv, o1y*inv, o1z*inv, o1w*inv);
}

// -------------- warp-per-token LayerNorm kernels ---------------------------
__device__ __forceinline__ void warp_ln_stats(float4 v0, float4 v1,
                                              float& mu, float& rstd)
{
    float s  = v0.x + v0.y + v0.z + v0.w + v1.x + v1.y + v1.z + v1.w;
    float s2 = v0.x*v0.x + v0.y*v0.y + v0.z*v0.z + v0.w*v0.w
             + v1.x*v1.x + v1.y*v1.y + v1.z*v1.z + v1.w*v1.w;
    #pragma unroll
    for (int o = 16; o; o >>= 1) {
        s  += __shfl_xor_sync(0xffffffffu, s,  o);
        s2 += __shfl_xor_sync(0xffffffffu, s2, o);
    }
    mu = s * (1.f / CDIM);
    float var = s2 * (1.f / CDIM) - mu * mu;
    rstd = rsqrtf(var + 1e-5f);
}

__global__ void __launch_bounds__(256)
ln_cat_w(const float* __restrict__ X, const float* __restrict__ Msg,
         const float* __restrict__ gw, const float* __restrict__ bw,
         float* __restrict__ cat)
{
    const int warp = threadIdx.x >> 5, lane = threadIdx.x & 31;
    const int t = blockIdx.x * 8 + warp;
    const float4* mrow = (const float4*)(Msg + (size_t)t * CDIM);
    float4 v0 = mrow[lane], v1 = mrow[lane + 32];
    float mu, rstd;
    warp_ln_stats(v0, v1, mu, rstd);

    const float4* g4 = (const float4*)gw;
    const float4* b4 = (const float4*)bw;
    float4 ga = g4[lane], gb = g4[lane + 32];
    float4 ba = b4[lane], bb = b4[lane + 32];
    float4 o0, o1;
    o0.x = (v0.x - mu) * rstd * ga.x + ba.x;
    o0.y = (v0.y - mu) * rstd * ga.y + ba.y;
    o0.z = (v0.z - mu) * rstd * ga.z + ba.z;
    o0.w = (v0.w - mu) * rstd * ga.w + ba.w;
    o1.x = (v1.x - mu) * rstd * gb.x + bb.x;
    o1.y = (v1.y - mu) * rstd * gb.y + bb.y;
    o1.z = (v1.z - mu) * rstd * gb.z + bb.z;
    o1.w = (v1.w - mu) * rstd * gb.w + bb.w;

    const float4* xrow = (const float4*)(X + (size_t)t * CDIM);
    float4* crow = (float4*)(cat + (size_t)t * 2 * CDIM);
    crow[lane]      = xrow[lane];
    crow[lane + 32] = xrow[lane + 32];
    crow[lane + 64] = o0;
    crow[lane + 96] = o1;
}

__global__ void __launch_bounds__(256)
ln_res_w(const float* __restrict__ Y, const float* __restrict__ gw,
         const float* __restrict__ bw, float* __restrict__ X)
{
    const int warp = threadIdx.x >> 5, lane = threadIdx.x & 31;
    const int t = blockIdx.x * 8 + warp;
    const float4* yrow = (const float4*)(Y + (size_t)t * CDIM);
    float4 v0 = yrow[lane], v1 = yrow[lane + 32];
    float mu, rstd;
    warp_ln_stats(v0, v1, mu, rstd);

    const float4* g4 = (const float4*)gw;
    const float4* b4 = (const float4*)bw;
    float4 ga = g4[lane], gb = g4[lane + 32];
    float4 ba = b4[lane], bb = b4[lane + 32];

    float4* xrow = (float4*)(X + (size_t)t * CDIM);
    float4 x0 = xrow[lane], x1 = xrow[lane + 32];
    x0.x += (v0.x - mu) * rstd * ga.x + ba.x;
    x0.y += (v0.y - mu) * rstd * ga.y + ba.y;
    x0.z += (v0.z - mu) * rstd * ga.z + ba.z;
    x0.w += (v0.w - mu) * rstd * ga.w + ba.w;
    x1.x += (v1.x - mu) * rstd * gb.x + bb.x;
    x1.y += (v1.y - mu) * rstd * gb.y + bb.y;
    x1.z += (v1.z - mu) * rstd * gb.z + bb.z;
    x1.w += (v1.w - mu) * rstd * gb.w + bb.w;
    xrow[lane]      = x0;
    xrow[lane + 32] = x1;
}

__global__ void copy_f(const float* __restrict__ in, float* __restrict__ out, int n)
{
    int i = blockIdx.x * 256 + threadIdx.x;
    if (i < n) out[i] = in[i];
}

__global__ void copy2_f(const float* __restrict__ in, float* __restrict__ o1,
                        float* __restrict__ o2, int n)
{
    int i = blockIdx.x * 256 + threadIdx.x;
    if (i < n) { float v = in[i]; o1[i] = v; o2[i] = v; }
}

// ===========================================================================
extern "C" void kernel_launch(void* const* d_in, const int* in_sizes, int n_in,
                              void* d_out, int out_size)
{
    const float* feat0 = (const float*)d_in[0];
    const float* feat1 = (const float*)d_in[1];
    const float* Wq = (const float*)d_in[2];
    const float* Wk = (const float*)d_in[3];
    const float* Wv = (const float*)d_in[4];
    const float* Wm = (const float*)d_in[5];
    const float* W1 = (const float*)d_in[6];
    const float* W2 = (const float*)d_in[7];
    const float* g1 = (const float*)d_in[8];
    const float* b1 = (const float*)d_in[9];
    const float* g2 = (const float*)d_in[10];
    const float* b2 = (const float*)d_in[11];
    float* out = (float*)d_out;

    float *simA, *simB, *koff00, *koff11, *koffA, *koffB;
    int *idx00, *idx11, *idx01, *idx10;
    float *F, *X, *KEall, *Vall, *Qb, *attn, *msg, *cat, *h1, *y;
    cudaGetSymbolAddress((void**)&simA, g_simA);
    cudaGetSymbolAddress((void**)&simB, g_simB);
    cudaGetSymbolAddress((void**)&koff00, g_koff00);
    cudaGetSymbolAddress((void**)&koff11, g_koff11);
    cudaGetSymbolAddress((void**)&koffA, g_koffA);
    cudaGetSymbolAddress((void**)&koffB, g_koffB);
    cudaGetSymbolAddress((void**)&idx00, g_idx00);
    cudaGetSymbolAddress((void**)&idx11, g_idx11);
    cudaGetSymbolAddress((void**)&idx01, g_idx01);
    cudaGetSymbolAddress((void**)&idx10, g_idx10);
    cudaGetSymbolAddress((void**)&F, g_F);
    cudaGetSymbolAddress((void**)&X, g_X);
    cudaGetSymbolAddress((void**)&KEall, g_KEall);
    cudaGetSymbolAddress((void**)&Vall, g_Vall);
    cudaGetSymbolAddress((void**)&Qb, g_Qb);
    cudaGetSymbolAddress((void**)&attn, g_attn);
    cudaGetSymbolAddress((void**)&msg, g_msg);
    cudaGetSymbolAddress((void**)&cat, g_cat);
    cudaGetSymbolAddress((void**)&h1, g_h1);
    cudaGetSymbolAddress((void**)&y, g_y);

    const dim3 simGrid((LTOK + 127) / 128, (LTOK + 127) / 128);
    const dim3 gKV(NLAYER * CDIM / 128, TTOK / 128);   // 16 x 75
    const dim3 g64n256(CDIM / 64, TTOK / 64);          // 4 x 150 = 600 CTAs
    const dim3 n512(2 * CDIM / 64, TTOK / 128);        // 8 x 75  = 600 CTAs

    // ---- stage 1: sim matrices (split-tf32), stats, top-K ----
    gemm_nt_tc<1><<<simGrid, 256>>>(feat0, feat0, simA, simA, SIM_SCALE);
    row_stats<<<LTOK, 256>>>(simA, koff00);
    topk16<<<LTOK, 256>>>(simA, koff00, idx00);

    gemm_nt_tc<1><<<simGrid, 256>>>(feat1, feat1, simA, simA, SIM_SCALE);
    row_stats<<<LTOK, 256>>>(simA, koff11);
    topk16<<<LTOK, 256>>>(simA, koff11, idx11);

    gemm_nt_tc<0><<<simGrid, 256>>>(feat0, feat1, simA, simB, SIM_SCALE);
    row_stats<<<LTOK, 256>>>(simA, koffA);
    row_stats<<<LTOK, 256>>>(simB, koffB);
    topk16<<<LTOK, 256>>>(simA, koffB, idx01);
    topk16<<<LTOK, 256>>>(simB, koffA, idx10);

    // ---- stage 2: concat features, all-layer K/V tables (layer-major) ----
    copy2_f<<<(LTOK * CDIM + 255) / 256, 256>>>(feat0, F, X, LTOK * CDIM);
    copy2_f<<<(LTOK * CDIM + 255) / 256, 256>>>(feat1, F + (size_t)LTOK * CDIM,
                                                X + (size_t)LTOK * CDIM, LTOK * CDIM);
    gemm128<1, 1><<<gKV, 256>>>(F, Wk, KEall, TTOK, NLAYER * CDIM, CDIM);
    gemm128<0, 1><<<gKV, 256>>>(F, Wv, Vall,  TTOK, NLAYER * CDIM, CDIM);

    // ---- stage 3: 8 encoder layers, both sides batched ----
    for (int i = 0; i < NLAYER; i++) {
        const float* wq = Wq + (size_t)i * CDIM * CDIM;
        const float* wm = Wm + (size_t)i * CDIM * CDIM;
        const float* w1 = W1 + (size_t)i * 2 * CDIM * 2 * CDIM;
        const float* w2 = W2 + (size_t)i * 2 * CDIM * CDIM;
        const float* gg1 = g1 + (size_t)i * CDIM;
        const float* bb1 = b1 + (size_t)i * CDIM;
        const float* gg2 = g2 + (size_t)i * CDIM;
        const float* bb2 = b2 + (size_t)i * CDIM;
        const bool cross = (i & 1);

        const int* idxA = cross ? idx01 : idx00;
        const int* idxB = cross ? idx10 : idx11;
        const int srcOffA = cross ? LTOK : 0;
        const int srcOffB = cross ? 0 : LTOK;

        const float* KEl = KEall + (size_t)i * TTOK * CDIM;
        const float* Vl  = Vall  + (size_t)i * TTOK * CDIM;

        gemm6464<1><<<g64n256, 256>>>(X, wq, Qb, TTOK, CDIM, CDIM);
        attn_w<<<TTOK / 8, 256>>>(Qb, KEl, Vl, idxA, idxB, srcOffA, srcOffB, attn);
        gemm6464<0><<<g64n256, 256>>>(attn, wm, msg, TTOK, CDIM, CDIM);
        ln_cat_w<<<TTOK / 8, 256>>>(X, msg, gg1, bb1, cat);
        gemm64<2><<<n512, 256>>>(cat, w1, h1, TTOK, 2 * CDIM, 2 * CDIM);
        gemm6464<0><<<g64n256, 256>>>(h1, w2, y, TTOK, CDIM, 2 * CDIM);
        ln_res_w<<<TTOK / 8, 256>>>(y, gg2, bb2, X);
    }

    // ---- stage 4: output ----
    copy_f<<<(TTOK * CDIM + 255) / 256, 256>>>(X, out, TTOK * CDIM);
}

// round 16
// speedup vs baseline: 1.0008x; 1.0008x over previous
#include <cuda_runtime.h>
#include <math.h>
#include <stdint.h>

#define LTOK 4800
#define TTOK 9600
#define CDIM 256
#define KSEL 16
#define NLAYER 8
#define SIM_SCALE (1.0f/25.6f)

// ------------------------- device scratch ---------------------------------
__device__ float g_simA[(size_t)LTOK * LTOK];
__device__ float g_simB[(size_t)LTOK * LTOK];
__device__ float g_koff00[LTOK];
__device__ float g_koff11[LTOK];
__device__ float g_koffA[LTOK];
__device__ float g_koffB[LTOK];
__device__ int   g_idx00[LTOK * KSEL];
__device__ int   g_idx11[LTOK * KSEL];
__device__ int   g_idx01[LTOK * KSEL];
__device__ int   g_idx10[LTOK * KSEL];
__device__ float g_F[TTOK * CDIM];
__device__ float g_X[TTOK * CDIM];
// layer-major: [layer][token][256]
__device__ float g_KEall[(size_t)NLAYER * TTOK * CDIM];
__device__ float g_Vall[(size_t)NLAYER * TTOK * CDIM];
__device__ float g_Qb[TTOK * CDIM];
__device__ float g_attn[TTOK * CDIM];
__device__ float g_msg[TTOK * CDIM];
__device__ float g_cat[TTOK * 2 * CDIM];
__device__ float g_h1[TTOK * 2 * CDIM];
__device__ float g_y[TTOK * CDIM];

__device__ __forceinline__ uint32_t f2tf(float f)
{
    uint32_t r;
    asm("cvt.rna.tf32.f32 %0, %1;" : "=r"(r) : "f"(f));
    return r;
}
__device__ __forceinline__ void split2(float v, uint32_t& h, uint32_t& l)
{
    h = f2tf(v);
    l = f2tf(v - __uint_as_float(h));
}

#define MMA_TF32(acc, a0,a1,a2,a3, b0,b1) \
    asm volatile("mma.sync.aligned.m16n8k8.row.col.f32.tf32.tf32.f32 " \
        "{%0,%1,%2,%3}, {%4,%5,%6,%7}, {%8,%9}, {%0,%1,%2,%3};\n" \
        : "+f"(acc[0]), "+f"(acc[1]), "+f"(acc[2]), "+f"(acc[3]) \
        : "r"(a0), "r"(a1), "r"(a2), "r"(a3), "r"(b0), "r"(b1))

// ======== split-tf32 sim GEMM: C = scale * (A @ B^T), fp32-accurate ========
// 3-term split (ah*bl + al*bh + ah*bh) is REQUIRED: R15 showed 2-term flips
// top-16 selections (rel_err 1.3e-2). Do not reduce precision here.
template <int SYM>
__global__ void __launch_bounds__(256, 2)
gemm_nt_tc(const float* __restrict__ A, const float* __restrict__ B,
           float* __restrict__ C, float* __restrict__ CT, float scale)
{
    if (SYM && blockIdx.y > blockIdx.x) return;

    __shared__ uint32_t Ah[128][20], Al[128][20], Bh[128][20], Bl[128][20];

    const int tid  = threadIdx.x;
    const int lane = tid & 31;
    const int warp = tid >> 5;
    const int wm   = warp & 3;
    const int wn   = warp >> 2;
    const int bm   = blockIdx.y * 128;
    const int bn   = blockIdx.x * 128;
    const int g    = lane >> 2;
    const int t4   = lane & 3;

    float acc[2][8][4];
    #pragma unroll
    for (int mt = 0; mt < 2; mt++)
        #pragma unroll
        for (int nt = 0; nt < 8; nt++)
            #pragma unroll
            for (int r = 0; r < 4; r++) acc[mt][nt][r] = 0.f;

    const int rr = tid >> 2;
    const int rk = (tid & 3) * 4;

    float4 pa[2], pb[2];

    #pragma unroll
    for (int j = 0; j < 2; j++) {
        int ra = min(bm + rr + 64 * j, LTOK - 1);
        int rb = min(bn + rr + 64 * j, LTOK - 1);
        pa[j] = *(const float4*)(A + (size_t)ra * CDIM + rk);
        pb[j] = *(const float4*)(B + (size_t)rb * CDIM + rk);
    }
    #pragma unroll
    for (int j = 0; j < 2; j++) {
        int r = rr + 64 * j;
        split2(pa[j].x, Ah[r][rk+0], Al[r][rk+0]);
        split2(pa[j].y, Ah[r][rk+1], Al[r][rk+1]);
        split2(pa[j].z, Ah[r][rk+2], Al[r][rk+2]);
        split2(pa[j].w, Ah[r][rk+3], Al[r][rk+3]);
        split2(pb[j].x, Bh[r][rk+0], Bl[r][rk+0]);
        split2(pb[j].y, Bh[r][rk+1], Bl[r][rk+1]);
        split2(pb[j].z, Bh[r][rk+2], Bl[r][rk+2]);
        split2(pb[j].w, Bh[r][rk+3], Bl[r][rk+3]);
    }
    __syncthreads();

    const int NT = CDIM / 16;
    for (int kt = 0; kt < NT; kt++) {
        if (kt + 1 < NT) {
            const int k0 = (kt + 1) << 4;
            #pragma unroll
            for (int j = 0; j < 2; j++) {
                int ra = min(bm + rr + 64 * j, LTOK - 1);
                int rb = min(bn + rr + 64 * j, LTOK - 1);
                pa[j] = *(const float4*)(A + (size_t)ra * CDIM + k0 + rk);
                pb[j] = *(const float4*)(B + (size_t)rb * CDIM + k0 + rk);
            }
        }

        #pragma unroll
        for (int ks = 0; ks < 16; ks += 8) {
            uint32_t ah[2][4], al[2][4];
            #pragma unroll
            for (int mt = 0; mt < 2; mt++) {
                int mrow = wm * 32 + mt * 16 + g;
                ah[mt][0] = Ah[mrow    ][ks + t4    ];
                ah[mt][1] = Ah[mrow + 8][ks + t4    ];
                ah[mt][2] = Ah[mrow    ][ks + t4 + 4];
                ah[mt][3] = Ah[mrow + 8][ks + t4 + 4];
                al[mt][0] = Al[mrow    ][ks + t4    ];
                al[mt][1] = Al[mrow + 8][ks + t4    ];
                al[mt][2] = Al[mrow    ][ks + t4 + 4];
                al[mt][3] = Al[mrow + 8][ks + t4 + 4];
            }
            uint32_t bh[8][2], bl[8][2];
            #pragma unroll
            for (int nt = 0; nt < 8; nt++) {
                int ncol = wn * 64 + nt * 8 + g;
                bh[nt][0] = Bh[ncol][ks + t4    ];
                bh[nt][1] = Bh[ncol][ks + t4 + 4];
                bl[nt][0] = Bl[ncol][ks + t4    ];
                bl[nt][1] = Bl[ncol][ks + t4 + 4];
            }
            #pragma unroll
            for (int mt = 0; mt < 2; mt++)
                #pragma unroll
                for (int nt = 0; nt < 8; nt++) {
                    MMA_TF32(acc[mt][nt], ah[mt][0], ah[mt][1], ah[mt][2], ah[mt][3],
                             bl[nt][0], bl[nt][1]);
                    MMA_TF32(acc[mt][nt], al[mt][0], al[mt][1], al[mt][2], al[mt][3],
                             bh[nt][0], bh[nt][1]);
                    MMA_TF32(acc[mt][nt], ah[mt][0], ah[mt][1], ah[mt][2], ah[mt][3],
                             bh[nt][0], bh[nt][1]);
                }
        }
        __syncthreads();

        if (kt + 1 < NT) {
            #pragma unroll
            for (int j = 0; j < 2; j++) {
                int r = rr + 64 * j;
                split2(pa[j].x, Ah[r][rk+0], Al[r][rk+0]);
                split2(pa[j].y, Ah[r][rk+1], Al[r][rk+1]);
                split2(pa[j].z, Ah[r][rk+2], Al[r][rk+2]);
                split2(pa[j].w, Ah[r][rk+3], Al[r][rk+3]);
                split2(pb[j].x, Bh[r][rk+0], Bl[r][rk+0]);
                split2(pb[j].y, Bh[r][rk+1], Bl[r][rk+1]);
                split2(pb[j].z, Bh[r][rk+2], Bl[r][rk+2]);
                split2(pb[j].w, Bh[r][rk+3], Bl[r][rk+3]);
            }
            __syncthreads();
        }
    }

    float* Cmir = SYM ? C : CT;
    const bool offdiag = !SYM || (blockIdx.y != blockIdx.x);
    #pragma unroll
    for (int mt = 0; mt < 2; mt++) {
        #pragma unroll
        for (int nt = 0; nt < 8; nt++) {
            int row0 = bm + wm * 32 + mt * 16 + g;
            int col  = bn + wn * 64 + nt * 8 + 2 * t4;
            float v0 = acc[mt][nt][0] * scale, v1 = acc[mt][nt][1] * scale;
            float v2 = acc[mt][nt][2] * scale, v3 = acc[mt][nt][3] * scale;
            if (col < LTOK) {
                if (row0 < LTOK)
                    *(float2*)(C + (size_t)row0 * LTOK + col) = make_float2(v0, v1);
                if (row0 + 8 < LTOK)
                    *(float2*)(C + (size_t)(row0 + 8) * LTOK + col) = make_float2(v2, v3);
            }
            if (offdiag || !SYM) {
                if (row0 < LTOK) {
                    if (col < LTOK)     Cmir[(size_t)col * LTOK + row0]       = v0;
                    if (col + 1 < LTOK) Cmir[(size_t)(col + 1) * LTOK + row0] = v1;
                }
                if (row0 + 8 < LTOK) {
                    if (col < LTOK)     Cmir[(size_t)col * LTOK + row0 + 8]       = v2;
                    if (col + 1 < LTOK) Cmir[(size_t)(col + 1) * LTOK + row0 + 8] = v3;
                }
            } else if (SYM) {
                if (row0 < LTOK) {
                    if (col < LTOK)     C[(size_t)col * LTOK + row0]       = v0;
                    if (col + 1 < LTOK) C[(size_t)(col + 1) * LTOK + row0] = v1;
                }
                if (row0 + 8 < LTOK) {
                    if (col < LTOK)     C[(size_t)col * LTOK + row0 + 8]       = v2;
                    if (col + 1 < LTOK) C[(size_t)(col + 1) * LTOK + row0 + 8] = v3;
                }
            }
        }
    }
}

// ====== tf32 GEMM, 128x128 tile (KV stacked) — single-sync double buffer ===
template <int ACT, int STACKB>
__global__ void __launch_bounds__(256, 2)
gemm128(const float* __restrict__ A, const float* __restrict__ B,
        float* __restrict__ C, int M, int N, int Kd)
{
    __shared__ uint32_t As[2][128][20];
    __shared__ uint32_t Bs[2][16][136];

    const int tid  = threadIdx.x;
    const int lane = tid & 31;
    const int warp = tid >> 5;
    const int wm   = warp & 3;
    const int wn   = warp >> 2;
    const int bm   = blockIdx.y * 128;
    const int bn   = blockIdx.x * 128;
    const int g  = lane >> 2;
    const int t4 = lane & 3;

    float acc[2][8][4];
    #pragma unroll
    for (int mt = 0; mt < 2; mt++)
        #pragma unroll
        for (int nt = 0; nt < 8; nt++)
            #pragma unroll
            for (int r = 0; r < 4; r++) acc[mt][nt][r] = 0.f;

    const int ar = tid >> 2;
    const int ak = (tid & 3) * 4;
    const int brow = tid >> 5;
    const int bcol = (tid & 31) * 4;

    const float* bptr;
    size_t bstride;
    if (STACKB) {
        int ncol = bn + bcol;
        bptr = B + (size_t)(ncol >> 8) * (CDIM * CDIM) + (ncol & 255);
        bstride = CDIM;
    } else {
        bptr = B + bn + bcol;
        bstride = (size_t)N;
    }

    const int NT = Kd >> 4;
    float4 pa[2], pb[2];

    #pragma unroll
    for (int j = 0; j < 2; j++) {
        pa[j] = *(const float4*)(A + (size_t)(bm + ar + 64 * j) * Kd + ak);
        pb[j] = *(const float4*)(bptr + (size_t)(brow + 8 * j) * bstride);
    }
    #pragma unroll
    for (int j = 0; j < 2; j++) {
        As[0][ar + 64 * j][ak + 0] = f2tf(pa[j].x);
        As[0][ar + 64 * j][ak + 1] = f2tf(pa[j].y);
        As[0][ar + 64 * j][ak + 2] = f2tf(pa[j].z);
        As[0][ar + 64 * j][ak + 3] = f2tf(pa[j].w);
        Bs[0][brow + 8 * j][bcol + 0] = f2tf(pb[j].x);
        Bs[0][brow + 8 * j][bcol + 1] = f2tf(pb[j].y);
        Bs[0][brow + 8 * j][bcol + 2] = f2tf(pb[j].z);
        Bs[0][brow + 8 * j][bcol + 3] = f2tf(pb[j].w);
    }
    __syncthreads();

    int buf = 0;
    for (int kt = 0; kt < NT; kt++) {
        if (kt + 1 < NT) {
            const int k0 = (kt + 1) << 4;
            #pragma unroll
            for (int j = 0; j < 2; j++) {
                pa[j] = *(const float4*)(A + (size_t)(bm + ar + 64 * j) * Kd + k0 + ak);
                pb[j] = *(const float4*)(bptr + (size_t)(k0 + brow + 8 * j) * bstride);
            }
        }

        #pragma unroll
        for (int ks = 0; ks < 16; ks += 8) {
            uint32_t af[2][4];
            #pragma unroll
            for (int mt = 0; mt < 2; mt++) {
                int mrow = wm * 32 + mt * 16 + g;
                af[mt][0] = As[buf][mrow    ][ks + t4    ];
                af[mt][1] = As[buf][mrow + 8][ks + t4    ];
                af[mt][2] = As[buf][mrow    ][ks + t4 + 4];
                af[mt][3] = As[buf][mrow + 8][ks + t4 + 4];
            }
            uint32_t bf[8][2];
            #pragma unroll
            for (int nt = 0; nt < 8; nt++) {
                int ncol = wn * 64 + nt * 8 + g;
                bf[nt][0] = Bs[buf][ks + t4    ][ncol];
                bf[nt][1] = Bs[buf][ks + t4 + 4][ncol];
            }
            #pragma unroll
            for (int mt = 0; mt < 2; mt++)
                #pragma unroll
                for (int nt = 0; nt < 8; nt++)
                    MMA_TF32(acc[mt][nt], af[mt][0], af[mt][1], af[mt][2], af[mt][3],
                             bf[nt][0], bf[nt][1]);
        }

        if (kt + 1 < NT) {
            int nb = buf ^ 1;
            #pragma unroll
            for (int j = 0; j < 2; j++) {
                As[nb][ar + 64 * j][ak + 0] = f2tf(pa[j].x);
                As[nb][ar + 64 * j][ak + 1] = f2tf(pa[j].y);
                As[nb][ar + 64 * j][ak + 2] = f2tf(pa[j].z);
                As[nb][ar + 64 * j][ak + 3] = f2tf(pa[j].w);
                Bs[nb][brow + 8 * j][bcol + 0] = f2tf(pb[j].x);
                Bs[nb][brow + 8 * j][bcol + 1] = f2tf(pb[j].y);
                Bs[nb][brow + 8 * j][bcol + 2] = f2tf(pb[j].z);
                Bs[nb][brow + 8 * j][bcol + 3] = f2tf(pb[j].w);
            }
            __syncthreads();
            buf = nb;
        }
    }

    #pragma unroll
    for (int mt = 0; mt < 2; mt++) {
        #pragma unroll
        for (int nt = 0; nt < 8; nt++) {
            int row = bm + wm * 32 + mt * 16 + g;
            int col = bn + wn * 64 + nt * 8 + 2 * t4;
            float v0 = acc[mt][nt][0], v1 = acc[mt][nt][1];
            float v2 = acc[mt][nt][2], v3 = acc[mt][nt][3];
            if (ACT == 1) {
                v0 = (v0 > 0.f) ? v0 + 1.f : expf(v0);
                v1 = (v1 > 0.f) ? v1 + 1.f : expf(v1);
                v2 = (v2 > 0.f) ? v2 + 1.f : expf(v2);
                v3 = (v3 > 0.f) ? v3 + 1.f : expf(v3);
            } else if (ACT == 2) {
                v0 = fmaxf(v0, 0.f); v1 = fmaxf(v1, 0.f);
                v2 = fmaxf(v2, 0.f); v3 = fmaxf(v3, 0.f);
            }
            if (STACKB) {
                size_t base = (size_t)(col >> 8) * ((size_t)TTOK * CDIM) + (col & 255);
                *(float2*)(C + base + (size_t)row * CDIM)       = make_float2(v0, v1);
                *(float2*)(C + base + (size_t)(row + 8) * CDIM) = make_float2(v2, v3);
            } else {
                *(float2*)(C + (size_t)row * N + col)       = make_float2(v0, v1);
                *(float2*)(C + (size_t)(row + 8) * N + col) = make_float2(v2, v3);
            }
        }
    }
}

// ====== tf32 GEMM, 128x64 tile — single-sync double buffer (W1) ============
template <int ACT>
__global__ void __launch_bounds__(256, 2)
gemm64(const float* __restrict__ A, const float* __restrict__ B,
       float* __restrict__ C, int M, int N, int Kd)
{
    __shared__ uint32_t As[2][128][20];
    __shared__ uint32_t Bs[2][16][72];

    const int tid  = threadIdx.x;
    const int lane = tid & 31;
    const int warp = tid >> 5;
    const int wm   = warp & 3;
    const int wn   = warp >> 2;
    const int bm   = blockIdx.y * 128;
    const int bn   = blockIdx.x * 64;
    const int g  = lane >> 2;
    const int t4 = lane & 3;

    float acc[2][4][4];
    #pragma unroll
    for (int mt = 0; mt < 2; mt++)
        #pragma unroll
        for (int nt = 0; nt < 4; nt++)
            #pragma unroll
            for (int r = 0; r < 4; r++) acc[mt][nt][r] = 0.f;

    const int ar = tid >> 2;
    const int ak = (tid & 3) * 4;
    const int brow = tid >> 4;
    const int bcol = (tid & 15) * 4;

    const int NT = Kd >> 4;
    float4 pa[2], pb;

    #pragma unroll
    for (int j = 0; j < 2; j++)
        pa[j] = *(const float4*)(A + (size_t)(bm + ar + 64 * j) * Kd + ak);
    pb = *(const float4*)(B + (size_t)brow * N + bn + bcol);
    #pragma unroll
    for (int j = 0; j < 2; j++) {
        As[0][ar + 64 * j][ak + 0] = f2tf(pa[j].x);
        As[0][ar + 64 * j][ak + 1] = f2tf(pa[j].y);
        As[0][ar + 64 * j][ak + 2] = f2tf(pa[j].z);
        As[0][ar + 64 * j][ak + 3] = f2tf(pa[j].w);
    }
    Bs[0][brow][bcol + 0] = f2tf(pb.x);
    Bs[0][brow][bcol + 1] = f2tf(pb.y);
    Bs[0][brow][bcol + 2] = f2tf(pb.z);
    Bs[0][brow][bcol + 3] = f2tf(pb.w);
    __syncthreads();

    int buf = 0;
    for (int kt = 0; kt < NT; kt++) {
        if (kt + 1 < NT) {
            const int k0 = (kt + 1) << 4;
            #pragma unroll
            for (int j = 0; j < 2; j++)
                pa[j] = *(const float4*)(A + (size_t)(bm + ar + 64 * j) * Kd + k0 + ak);
            pb = *(const float4*)(B + (size_t)(k0 + brow) * N + bn + bcol);
        }

        #pragma unroll
        for (int ks = 0; ks < 16; ks += 8) {
            uint32_t af[2][4];
            #pragma unroll
            for (int mt = 0; mt < 2; mt++) {
                int mrow = wm * 32 + mt * 16 + g;
                af[mt][0] = As[buf][mrow    ][ks + t4    ];
                af[mt][1] = As[buf][mrow + 8][ks + t4    ];
                af[mt][2] = As[buf][mrow    ][ks + t4 + 4];
                af[mt][3] = As[buf][mrow + 8][ks + t4 + 4];
            }
            uint32_t bf[4][2];
            #pragma unroll
            for (int nt = 0; nt < 4; nt++) {
                int ncol = wn * 32 + nt * 8 + g;
                bf[nt][0] = Bs[buf][ks + t4    ][ncol];
                bf[nt][1] = Bs[buf][ks + t4 + 4][ncol];
            }
            #pragma unroll
            for (int mt = 0; mt < 2; mt++)
                #pragma unroll
                for (int nt = 0; nt < 4; nt++)
                    MMA_TF32(acc[mt][nt], af[mt][0], af[mt][1], af[mt][2], af[mt][3],
                             bf[nt][0], bf[nt][1]);
        }

        if (kt + 1 < NT) {
            int nb = buf ^ 1;
            #pragma unroll
            for (int j = 0; j < 2; j++) {
                As[nb][ar + 64 * j][ak + 0] = f2tf(pa[j].x);
                As[nb][ar + 64 * j][ak + 1] = f2tf(pa[j].y);
                As[nb][ar + 64 * j][ak + 2] = f2tf(pa[j].z);
                As[nb][ar + 64 * j][ak + 3] = f2tf(pa[j].w);
            }
            Bs[nb][brow][bcol + 0] = f2tf(pb.x);
            Bs[nb][brow][bcol + 1] = f2tf(pb.y);
            Bs[nb][brow][bcol + 2] = f2tf(pb.z);
            Bs[nb][brow][bcol + 3] = f2tf(pb.w);
            __syncthreads();
            buf = nb;
        }
    }

    #pragma unroll
    for (int mt = 0; mt < 2; mt++) {
        #pragma unroll
        for (int nt = 0; nt < 4; nt++) {
            int row = bm + wm * 32 + mt * 16 + g;
            int col = bn + wn * 32 + nt * 8 + 2 * t4;
            float v0 = acc[mt][nt][0], v1 = acc[mt][nt][1];
            float v2 = acc[mt][nt][2], v3 = acc[mt][nt][3];
            if (ACT == 1) {
                v0 = (v0 > 0.f) ? v0 + 1.f : expf(v0);
                v1 = (v1 > 0.f) ? v1 + 1.f : expf(v1);
                v2 = (v2 > 0.f) ? v2 + 1.f : expf(v2);
                v3 = (v3 > 0.f) ? v3 + 1.f : expf(v3);
            } else if (ACT == 2) {
                v0 = fmaxf(v0, 0.f); v1 = fmaxf(v1, 0.f);
                v2 = fmaxf(v2, 0.f); v3 = fmaxf(v3, 0.f);
            }
            *(float2*)(C + (size_t)row * N + col)       = make_float2(v0, v1);
            *(float2*)(C + (size_t)(row + 8) * N + col) = make_float2(v2, v3);
        }
    }
}

// ====== tf32 GEMM, 64x64 tile — wave-balanced, 3 CTAs/SM (Q/Wm/W2) =========
template <int ACT>
__global__ void __launch_bounds__(256, 3)
gemm6464(const float* __restrict__ A, const float* __restrict__ B,
         float* __restrict__ C, int M, int N, int Kd)
{
    __shared__ uint32_t As[2][64][20];
    __shared__ uint32_t Bs[2][16][72];

    const int tid  = threadIdx.x;
    const int lane = tid & 31;
    const int warp = tid >> 5;
    const int wm   = warp & 1;
    const int wn   = warp >> 1;
    const int bm   = blockIdx.y * 64;
    const int bn   = blockIdx.x * 64;
    const int g  = lane >> 2;
    const int t4 = lane & 3;

    float acc[2][2][4];
    #pragma unroll
    for (int mt = 0; mt < 2; mt++)
        #pragma unroll
        for (int nt = 0; nt < 2; nt++)
            #pragma unroll
            for (int r = 0; r < 4; r++) acc[mt][nt][r] = 0.f;

    const int ar = tid >> 2;
    const int ak = (tid & 3) * 4;
    const int brow = tid >> 4;
    const int bcol = (tid & 15) * 4;

    const int NT = Kd >> 4;
    float4 pa, pb;

    pa = *(const float4*)(A + (size_t)(bm + ar) * Kd + ak);
    pb = *(const float4*)(B + (size_t)brow * N + bn + bcol);
    As[0][ar][ak + 0] = f2tf(pa.x);
    As[0][ar][ak + 1] = f2tf(pa.y);
    As[0][ar][ak + 2] = f2tf(pa.z);
    As[0][ar][ak + 3] = f2tf(pa.w);
    Bs[0][brow][bcol + 0] = f2tf(pb.x);
    Bs[0][brow][bcol + 1] = f2tf(pb.y);
    Bs[0][brow][bcol + 2] = f2tf(pb.z);
    Bs[0][brow][bcol + 3] = f2tf(pb.w);
    __syncthreads();

    int buf = 0;
    for (int kt = 0; kt < NT; kt++) {
        if (kt + 1 < NT) {
            const int k0 = (kt + 1) << 4;
            pa = *(const float4*)(A + (size_t)(bm + ar) * Kd + k0 + ak);
            pb = *(const float4*)(B + (size_t)(k0 + brow) * N + bn + bcol);
        }

        #pragma unroll
        for (int ks = 0; ks < 16; ks += 8) {
            uint32_t af[2][4];
            #pragma unroll
            for (int mt = 0; mt < 2; mt++) {
                int mrow = wm * 32 + mt * 16 + g;
                af[mt][0] = As[buf][mrow    ][ks + t4    ];
                af[mt][1] = As[buf][mrow + 8][ks + t4    ];
                af[mt][2] = As[buf][mrow    ][ks + t4 + 4];
                af[mt][3] = As[buf][mrow + 8][ks + t4 + 4];
            }
            uint32_t bf[2][2];
            #pragma unroll
            for (int nt = 0; nt < 2; nt++) {
                int ncol = wn * 16 + nt * 8 + g;
                bf[nt][0] = Bs[buf][ks + t4    ][ncol];
                bf[nt][1] = Bs[buf][ks + t4 + 4][ncol];
            }
            #pragma unroll
            for (int mt = 0; mt < 2; mt++)
                #pragma unroll
                for (int nt = 0; nt < 2; nt++)
                    MMA_TF32(acc[mt][nt], af[mt][0], af[mt][1], af[mt][2], af[mt][3],
                             bf[nt][0], bf[nt][1]);
        }

        if (kt + 1 < NT) {
            int nb = buf ^ 1;
            As[nb][ar][ak + 0] = f2tf(pa.x);
            As[nb][ar][ak + 1] = f2tf(pa.y);
            As[nb][ar][ak + 2] = f2tf(pa.z);
            As[nb][ar][ak + 3] = f2tf(pa.w);
            Bs[nb][brow][bcol + 0] = f2tf(pb.x);
            Bs[nb][brow][bcol + 1] = f2tf(pb.y);
            Bs[nb][brow][bcol + 2] = f2tf(pb.z);
            Bs[nb][brow][bcol + 3] = f2tf(pb.w);
            __syncthreads();
            buf = nb;
        }
    }

    #pragma unroll
    for (int mt = 0; mt < 2; mt++) {
        #pragma unroll
        for (int nt = 0; nt < 2; nt++) {
            int row = bm + wm * 32 + mt * 16 + g;
            int col = bn + wn * 16 + nt * 8 + 2 * t4;
            float v0 = acc[mt][nt][0], v1 = acc[mt][nt][1];
            float v2 = acc[mt][nt][2], v3 = acc[mt][nt][3];
            if (ACT == 1) {
                v0 = (v0 > 0.f) ? v0 + 1.f : expf(v0);
                v1 = (v1 > 0.f) ? v1 + 1.f : expf(v1);
                v2 = (v2 > 0.f) ? v2 + 1.f : expf(v2);
                v3 = (v3 > 0.f) ? v3 + 1.f : expf(v3);
            } else if (ACT == 2) {
                v0 = fmaxf(v0, 0.f); v1 = fmaxf(v1, 0.f);
                v2 = fmaxf(v2, 0.f); v3 = fmaxf(v3, 0.f);
            }
            *(float2*)(C + (size_t)row * N + col)       = make_float2(v0, v1);
            *(float2*)(C + (size_t)(row + 8) * N + col) = make_float2(v2, v3);
        }
    }
}

// --------------- per-row logsumexp key offset (single pass) ----------------
__global__ void __launch_bounds__(256)
row_stats(const float* __restrict__ S, float* __restrict__ koff)
{
    const int row = blockIdx.x;
    const float* r = S + (size_t)row * LTOK;
    const int tid = threadIdx.x;
    __shared__ float sm[8], ss[8];

    float m = -1e30f, s = 0.f;
    for (int j = tid; j < LTOK; j += 256) {
        float x = r[j];
        if (x > m) { s = s * expf(m - x) + 1.f; m = x; }
        else       { s += expf(x - m); }
    }
    #pragma unroll
    for (int o = 16; o; o >>= 1) {
        float om = __shfl_down_sync(0xffffffffu, m, o);
        float os = __shfl_down_sync(0xffffffffu, s, o);
        float M = fmaxf(m, om);
        s = s * expf(m - M) + os * expf(om - M);
        m = M;
    }
    if ((tid & 31) == 0) { sm[tid >> 5] = m; ss[tid >> 5] = s; }
    __syncthreads();
    if (tid < 32) {
        float mm = (tid < 8) ? sm[tid] : -1e30f;
        float sv = (tid < 8) ? ss[tid] : 0.f;
        #pragma unroll
        for (int o = 4; o; o >>= 1) {
            float om = __shfl_down_sync(0xffffffffu, mm, o);
            float os = __shfl_down_sync(0xffffffffu, sv, o);
            float M = fmaxf(mm, om);
            sv = sv * expf(mm - M) + os * expf(om - M);
            mm = M;
        }
        if (tid == 0) koff[row] = mm + logf(sv);
    }
}

// -------------- top-16 per row (float4-vectorized scan) --------------------
__global__ void __launch_bounds__(256)
topk16(const float* __restrict__ S, const float* __restrict__ koff,
       int* __restrict__ out)
{
    const int row = blockIdx.x;
    const int tid = threadIdx.x;
    float lv[KSEL];
    int   li[KSEL];
    #pragma unroll
    for (int s = 0; s < KSEL; s++) { lv[s] = -1e30f; li[s] = 0x7fffffff; }

    const float4* r4 = (const float4*)(S + (size_t)row * LTOK);
    const float4* k4 = (const float4*)koff;
    const int NJ4 = LTOK / 4;
    for (int j4 = tid; j4 < NJ4; j4 += 256) {
        const float4 rv4 = r4[j4];
        const float4 kv4 = k4[j4];
        float cand[4] = {2.f * rv4.x - kv4.x, 2.f * rv4.y - kv4.y,
                         2.f * rv4.z - kv4.z, 2.f * rv4.w - kv4.w};
        #pragma unroll
        for (int c = 0; c < 4; c++) {
            float nv = cand[c];
            int ni = j4 * 4 + c;
            if (nv > lv[KSEL - 1] || (nv == lv[KSEL - 1] && ni < li[KSEL - 1])) {
                #pragma unroll
                for (int s = 0; s < KSEL; s++) {
                    bool better = (nv > lv[s]) || (nv == lv[s] && ni < li[s]);
                    if (better) {
                        float tv = lv[s]; int ti = li[s];
                        lv[s] = nv; li[s] = ni; nv = tv; ni = ti;
                    }
                }
            }
        }
    }

    __shared__ float tv[256 * KSEL];
    __shared__ int   ti[256 * KSEL];
    __shared__ float rv[256];
    __shared__ int   ri[256];
    __shared__ int   rt[256];
    #pragma unroll
    for (int s = 0; s < KSEL; s++) { tv[tid * KSEL + s] = lv[s]; ti[tid * KSEL + s] = li[s]; }
    __syncthreads();

    int hp = 0;
    for (int k = 0; k < KSEL; k++) {
        rv[tid] = (hp < KSEL) ? tv[tid * KSEL + hp] : -1e30f;
        ri[tid] = (hp < KSEL) ? ti[tid * KSEL + hp] : 0x7fffffff;
        rt[tid] = tid;
        __syncthreads();
        for (int o = 128; o; o >>= 1) {
            if (tid < o) {
                float ov = rv[tid + o]; int oi = ri[tid + o];
                if (ov > rv[tid] || (ov == rv[tid] && oi < ri[tid])) {
                    rv[tid] = ov; ri[tid] = oi; rt[tid] = rt[tid + o];
                }
            }
            __syncthreads();
        }
        if (tid == 0) out[row * KSEL + k] = ri[0];
        if (tid == rt[0]) hp++;
        __syncthreads();
    }
}

// ---- linear attention: warp per token, shfl-only, float4 (no smem/bars) ---
__global__ void __launch_bounds__(256)
attn_w(const float* __restrict__ Q,
       const float* __restrict__ KE, const float* __restrict__ V,
       const int* __restrict__ idxA, const int* __restrict__ idxB,
       int srcOffA, int srcOffB,
       float* __restrict__ out)
{
    const int warp = threadIdx.x >> 5, lane = threadIdx.x & 31;
    const int t = blockIdx.x * 8 + warp;
    const int side = (t >= LTOK);
    const int tl = side ? t - LTOK : t;
    const int* idx = side ? idxB : idxA;
    const int srcOff = side ? srcOffB : srcOffA;

    int myidx = 0;
    if (lane < KSEL) myidx = srcOff + idx[tl * KSEL + lane];

    const float4* Q4  = (const float4*)Q;
    const float4* KE4 = (const float4*)KE;
    const float4* V4  = (const float4*)V;

    const float4 q0 = Q4[(size_t)t * 64 + lane * 2];
    const float4 q1 = Q4[(size_t)t * 64 + lane * 2 + 1];

    float o0x=0.f,o0y=0.f,o0z=0.f,o0w=0.f, o1x=0.f,o1y=0.f,o1z=0.f,o1w=0.f;
    float zs = 1e-6f;

    #pragma unroll
    for (int s = 0; s < KSEL; s++) {
        const int src = __shfl_sync(0xffffffffu, myidx, s);
        const size_t base = (size_t)src * 64 + lane * 2;
        const float4 k0 = KE4[base];
        const float4 k1 = KE4[base + 1];
        float p = q0.x*k0.x + q0.y*k0.y + q0.z*k0.z + q0.w*k0.w
                + q1.x*k1.x + q1.y*k1.y + q1.z*k1.z + q1.w*k1.w;
        p += __shfl_down_sync(0xffffffffu, p, 2);
        p += __shfl_down_sync(0xffffffffu, p, 1);
        const float sc = __shfl_sync(0xffffffffu, p, lane & 28);
        zs += sc;
        const float4 v0 = V4[base];
        const float4 v1 = V4[base + 1];
        o0x += sc * v0.x; o0y += sc * v0.y; o0z += sc * v0.z; o0w += sc * v0.w;
        o1x += sc * v1.x; o1y += sc * v1.y; o1z += sc * v1.z; o1w += sc * v1.w;
    }

    const float inv = 1.f / zs;
    float4* O4 = (float4*)out;
    O4[(size_t)t * 64 + lane * 2]     = make_float4(o0x*inv, o0y*inv, o0z*inv, o0w*inv);
    O4[(size_t)t * 64 + lane * 2 + 1] = make_float4(o1x*inv, o1y*inv, o1z*inv, o1w*inv);
}

// -------------- warp-per-token LayerNorm kernels ---------------------------
__device__ __forceinline__ void warp_ln_stats(float4 v0, float4 v1,
                                              float& mu, float& rstd)
{
    float s  = v0.x + v0.y + v0.z + v0.w + v1.x + v1.y + v1.z + v1.w;
    float s2 = v0.x*v0.x + v0.y*v0.y + v0.z*v0.z + v0.w*v0.w
             + v1.x*v1.x + v1.y*v1.y + v1.z*v1.z + v1.w*v1.w;
    #pragma unroll
    for (int o = 16; o; o >>= 1) {
        s  += __shfl_xor_sync(0xffffffffu, s,  o);
        s2 += __shfl_xor_sync(0xffffffffu, s2, o);
    }
    mu = s * (1.f / CDIM);
    float var = s2 * (1.f / CDIM) - mu * mu;
    rstd = rsqrtf(var + 1e-5f);
}

__global__ void __launch_bounds__(256)
ln_cat_w(const float* __restrict__ X, const float* __restrict__ Msg,
         const float* __restrict__ gw, const float* __restrict__ bw,
         float* __restrict__ cat)
{
    const int warp = threadIdx.x >> 5, lane = threadIdx.x & 31;
    const int t = blockIdx.x * 8 + warp;
    const float4* mrow = (const float4*)(Msg + (size_t)t * CDIM);
    float4 v0 = mrow[lane], v1 = mrow[lane + 32];
    float mu, rstd;
    warp_ln_stats(v0, v1, mu, rstd);

    const float4* g4 = (const float4*)gw;
    const float4* b4 = (const float4*)bw;
    float4 ga = g4[lane], gb = g4[lane + 32];
    float4 ba = b4[lane], bb = b4[lane + 32];
    float4 o0, o1;
    o0.x = (v0.x - mu) * rstd * ga.x + ba.x;
    o0.y = (v0.y - mu) * rstd * ga.y + ba.y;
    o0.z = (v0.z - mu) * rstd * ga.z + ba.z;
    o0.w = (v0.w - mu) * rstd * ga.w + ba.w;
    o1.x = (v1.x - mu) * rstd * gb.x + bb.x;
    o1.y = (v1.y - mu) * rstd * gb.y + bb.y;
    o1.z = (v1.z - mu) * rstd * gb.z + bb.z;
    o1.w = (v1.w - mu) * rstd * gb.w + bb.w;

    const float4* xrow = (const float4*)(X + (size_t)t * CDIM);
    float4* crow = (float4*)(cat + (size_t)t * 2 * CDIM);
    crow[lane]      = xrow[lane];
    crow[lane + 32] = xrow[lane + 32];
    crow[lane + 64] = o0;
    crow[lane + 96] = o1;
}

__global__ void __launch_bounds__(256)
ln_res_w(const float* __restrict__ Y, const float* __restrict__ gw,
         const float* __restrict__ bw, float* __restrict__ X)
{
    const int warp = threadIdx.x >> 5, lane = threadIdx.x & 31;
    const int t = blockIdx.x * 8 + warp;
    const float4* yrow = (const float4*)(Y + (size_t)t * CDIM);
    float4 v0 = yrow[lane], v1 = yrow[lane + 32];
    float mu, rstd;
    warp_ln_stats(v0, v1, mu, rstd);

    const float4* g4 = (const float4*)gw;
    const float4* b4 = (const float4*)bw;
    float4 ga = g4[lane], gb = g4[lane + 32];
    float4 ba = b4[lane], bb = b4[lane + 32];

    float4* xrow = (float4*)(X + (size_t)t * CDIM);
    float4 x0 = xrow[lane], x1 = xrow[lane + 32];
    x0.x += (v0.x - mu) * rstd * ga.x + ba.x;
    x0.y += (v0.y - mu) * rstd * ga.y + ba.y;
    x0.z += (v0.z - mu) * rstd * ga.z + ba.z;
    x0.w += (v0.w - mu) * rstd * ga.w + ba.w;
    x1.x += (v1.x - mu) * rstd * gb.x + bb.x;
    x1.y += (v1.y - mu) * rstd * gb.y + bb.y;
    x1.z += (v1.z - mu) * rstd * gb.z + bb.z;
    x1.w += (v1.w - mu) * rstd * gb.w + bb.w;
    xrow[lane]      = x0;
    xrow[lane + 32] = x1;
}

__global__ void copy_f(const float* __restrict__ in, float* __restrict__ out, int n)
{
    int i = blockIdx.x * 256 + threadIdx.x;
    if (i < n) out[i] = in[i];
}

__global__ void copy2_f(const float* __restrict__ in, float* __restrict__ o1,
                        float* __restrict__ o2, int n)
{
    int i = blockIdx.x * 256 + threadIdx.x;
    if (i < n) { float v = in[i]; o1[i] = v; o2[i] = v; }
}

// ===========================================================================
extern "C" void kernel_launch(void* const* d_in, const int* in_sizes, int n_in,
                              void* d_out, int out_size)
{
    const float* feat0 = (const float*)d_in[0];
    const float* feat1 = (const float*)d_in[1];
    const float* Wq = (const float*)d_in[2];
    const float* Wk = (const float*)d_in[3];
    const float* Wv = (const float*)d_in[4];
    const float* Wm = (const float*)d_in[5];
    const float* W1 = (const float*)d_in[6];
    const float* W2 = (const float*)d_in[7];
    const float* g1 = (const float*)d_in[8];
    const float* b1 = (const float*)d_in[9];
    const float* g2 = (const float*)d_in[10];
    const float* b2 = (const float*)d_in[11];
    float* out = (float*)d_out;

    float *simA, *simB, *koff00, *koff11, *koffA, *koffB;
    int *idx00, *idx11, *idx01, *idx10;
    float *F, *X, *KEall, *Vall, *Qb, *attn, *msg, *cat, *h1, *y;
    cudaGetSymbolAddress((void**)&simA, g_simA);
    cudaGetSymbolAddress((void**)&simB, g_simB);
    cudaGetSymbolAddress((void**)&koff00, g_koff00);
    cudaGetSymbolAddress((void**)&koff11, g_koff11);
    cudaGetSymbolAddress((void**)&koffA, g_koffA);
    cudaGetSymbolAddress((void**)&koffB, g_koffB);
    cudaGetSymbolAddress((void**)&idx00, g_idx00);
    cudaGetSymbolAddress((void**)&idx11, g_idx11);
    cudaGetSymbolAddress((void**)&idx01, g_idx01);
    cudaGetSymbolAddress((void**)&idx10, g_idx10);
    cudaGetSymbolAddress((void**)&F, g_F);
    cudaGetSymbolAddress((void**)&X, g_X);
    cudaGetSymbolAddress((void**)&KEall, g_KEall);
    cudaGetSymbolAddress((void**)&Vall, g_Vall);
    cudaGetSymbolAddress((void**)&Qb, g_Qb);
    cudaGetSymbolAddress((void**)&attn, g_attn);
    cudaGetSymbolAddress((void**)&msg, g_msg);
    cudaGetSymbolAddress((void**)&cat, g_cat);
    cudaGetSymbolAddress((void**)&h1, g_h1);
    cudaGetSymbolAddress((void**)&y, g_y);

    const dim3 simGrid((LTOK + 127) / 128, (LTOK + 127) / 128);
    const dim3 gKV(NLAYER * CDIM / 128, TTOK / 128);   // 16 x 75
    const dim3 g64n256(CDIM / 64, TTOK / 64);          // 4 x 150 = 600 CTAs
    const dim3 n512(2 * CDIM / 64, TTOK / 128);        // 8 x 75  = 600 CTAs

    // ---- stage 1: sim matrices (3-term split-tf32), stats, top-K ----
    gemm_nt_tc<1><<<simGrid, 256>>>(feat0, feat0, simA, simA, SIM_SCALE);
    row_stats<<<LTOK, 256>>>(simA, koff00);
    topk16<<<LTOK, 256>>>(simA, koff00, idx00);

    gemm_nt_tc<1><<<simGrid, 256>>>(feat1, feat1, simA, simA, SIM_SCALE);
    row_stats<<<LTOK, 256>>>(simA, koff11);
    topk16<<<LTOK, 256>>>(simA, koff11, idx11);

    gemm_nt_tc<0><<<simGrid, 256>>>(feat0, feat1, simA, simB, SIM_SCALE);
    row_stats<<<LTOK, 256>>>(simA, koffA);
    row_stats<<<LTOK, 256>>>(simB, koffB);
    topk16<<<LTOK, 256>>>(simA, koffB, idx01);
    topk16<<<LTOK, 256>>>(simB, koffA, idx10);

    // ---- stage 2: concat features, all-layer K/V tables (layer-major) ----
    copy2_f<<<(LTOK * CDIM + 255) / 256, 256>>>(feat0, F, X, LTOK * CDIM);
    copy2_f<<<(LTOK * CDIM + 255) / 256, 256>>>(feat1, F + (size_t)LTOK * CDIM,
                                                X + (size_t)LTOK * CDIM, LTOK * CDIM);
    gemm128<1, 1><<<gKV, 256>>>(F, Wk, KEall, TTOK, NLAYER * CDIM, CDIM);
    gemm128<0, 1><<<gKV, 256>>>(F, Wv, Vall,  TTOK, NLAYER * CDIM, CDIM);

    // ---- stage 3: 8 encoder layers, both sides batched ----
    for (int i = 0; i < NLAYER; i++) {
        const float* wq = Wq + (size_t)i * CDIM * CDIM;
        const float* wm = Wm + (size_t)i * CDIM * CDIM;
        const float* w1 = W1 + (size_t)i * 2 * CDIM * 2 * CDIM;
        const float* w2 = W2 + (size_t)i * 2 * CDIM * CDIM;
        const float* gg1 = g1 + (size_t)i * CDIM;
        const float* bb1 = b1 + (size_t)i * CDIM;
        const float* gg2 = g2 + (size_t)i * CDIM;
        const float* bb2 = b2 + (size_t)i * CDIM;
        const bool cross = (i & 1);

        const int* idxA = cross ? idx01 : idx00;
        const int* idxB = cross ? idx10 : idx11;
        const int srcOffA = cross ? LTOK : 0;
        const int srcOffB = cross ? 0 : LTOK;

        const float* KEl = KEall + (size_t)i * TTOK * CDIM;
        const float* Vl  = Vall  + (size_t)i * TTOK * CDIM;

        gemm6464<1><<<g64n256, 256>>>(X, wq, Qb, TTOK, CDIM, CDIM);
        attn_w<<<TTOK / 8, 256>>>(Qb, KEl, Vl, idxA, idxB, srcOffA, srcOffB, attn);
        gemm6464<0><<<g64n256, 256>>>(attn, wm, msg, TTOK, CDIM, CDIM);
        ln_cat_w<<<TTOK / 8, 256>>>(X, msg, gg1, bb1, cat);
        gemm64<2><<<n512, 256>>>(cat, w1, h1, TTOK, 2 * CDIM, 2 * CDIM);
        gemm6464<0><<<g64n256, 256>>>(h1, w2, y, TTOK, CDIM, 2 * CDIM);
        ln_res_w<<<TTOK / 8, 256>>>(y, gg2, bb2, X);
    }

    // ---- stage 4: output ----
    copy_f<<<(TTOK * CDIM + 255) / 256, 256>>>(X, out, TTOK * CDIM);
}

// round 17
// speedup vs baseline: 1.0260x; 1.0251x over previous
#include <cuda_runtime.h>
#include <math.h>
#include <stdint.h>

#define LTOK 4800
#define TTOK 9600
#define CDIM 256
#define KSEL 16
#define NLAYER 8
#define SIM_SCALE (1.0f/25.6f)

// ------------------------- device scratch ---------------------------------
__device__ float g_simA[(size_t)LTOK * LTOK];
__device__ float g_simB[(size_t)LTOK * LTOK];
__device__ float g_koff00[LTOK];
__device__ float g_koff11[LTOK];
__device__ float g_koffA[LTOK];
__device__ float g_koffB[LTOK];
__device__ int   g_idx00[LTOK * KSEL];
__device__ int   g_idx11[LTOK * KSEL];
__device__ int   g_idx01[LTOK * KSEL];
__device__ int   g_idx10[LTOK * KSEL];
__device__ float g_F[TTOK * CDIM];
__device__ float g_X[TTOK * CDIM];
// layer-major: [layer][token][256]
__device__ float g_KEall[(size_t)NLAYER * TTOK * CDIM];
__device__ float g_Vall[(size_t)NLAYER * TTOK * CDIM];
__device__ float g_Qb[TTOK * CDIM];
__device__ float g_attn[TTOK * CDIM];
__device__ float g_msg[TTOK * CDIM];
__device__ float g_cat[TTOK * 2 * CDIM];
__device__ float g_h1[TTOK * 2 * CDIM];
__device__ float g_y[TTOK * CDIM];

__device__ __forceinline__ uint32_t f2tf(float f)
{
    uint32_t r;
    asm("cvt.rna.tf32.f32 %0, %1;" : "=r"(r) : "f"(f));
    return r;
}
__device__ __forceinline__ void split2(float v, uint32_t& h, uint32_t& l)
{
    h = f2tf(v);
    l = f2tf(v - __uint_as_float(h));
}

#define MMA_TF32(acc, a0,a1,a2,a3, b0,b1) \
    asm volatile("mma.sync.aligned.m16n8k8.row.col.f32.tf32.tf32.f32 " \
        "{%0,%1,%2,%3}, {%4,%5,%6,%7}, {%8,%9}, {%0,%1,%2,%3};\n" \
        : "+f"(acc[0]), "+f"(acc[1]), "+f"(acc[2]), "+f"(acc[3]) \
        : "r"(a0), "r"(a1), "r"(a2), "r"(a3), "r"(b0), "r"(b1))

// ======== split-tf32 sim GEMM: C = scale * (A @ B^T), fp32-accurate ========
// 3-term split (ah*bl + al*bh + ah*bh) is REQUIRED: R15 showed 2-term flips
// top-16 selections (rel_err 1.3e-2). Do not reduce precision here.
template <int SYM>
__global__ void __launch_bounds__(256, 2)
gemm_nt_tc(const float* __restrict__ A, const float* __restrict__ B,
           float* __restrict__ C, float* __restrict__ CT, float scale)
{
    if (SYM && blockIdx.y > blockIdx.x) return;

    __shared__ uint32_t Ah[128][20], Al[128][20], Bh[128][20], Bl[128][20];

    const int tid  = threadIdx.x;
    const int lane = tid & 31;
    const int warp = tid >> 5;
    const int wm   = warp & 3;
    const int wn   = warp >> 2;
    const int bm   = blockIdx.y * 128;
    const int bn   = blockIdx.x * 128;
    const int g    = lane >> 2;
    const int t4   = lane & 3;

    float acc[2][8][4];
    #pragma unroll
    for (int mt = 0; mt < 2; mt++)
        #pragma unroll
        for (int nt = 0; nt < 8; nt++)
            #pragma unroll
            for (int r = 0; r < 4; r++) acc[mt][nt][r] = 0.f;

    const int rr = tid >> 2;
    const int rk = (tid & 3) * 4;

    float4 pa[2], pb[2];

    #pragma unroll
    for (int j = 0; j < 2; j++) {
        int ra = min(bm + rr + 64 * j, LTOK - 1);
        int rb = min(bn + rr + 64 * j, LTOK - 1);
        pa[j] = *(const float4*)(A + (size_t)ra * CDIM + rk);
        pb[j] = *(const float4*)(B + (size_t)rb * CDIM + rk);
    }
    #pragma unroll
    for (int j = 0; j < 2; j++) {
        int r = rr + 64 * j;
        split2(pa[j].x, Ah[r][rk+0], Al[r][rk+0]);
        split2(pa[j].y, Ah[r][rk+1], Al[r][rk+1]);
        split2(pa[j].z, Ah[r][rk+2], Al[r][rk+2]);
        split2(pa[j].w, Ah[r][rk+3], Al[r][rk+3]);
        split2(pb[j].x, Bh[r][rk+0], Bl[r][rk+0]);
        split2(pb[j].y, Bh[r][rk+1], Bl[r][rk+1]);
        split2(pb[j].z, Bh[r][rk+2], Bl[r][rk+2]);
        split2(pb[j].w, Bh[r][rk+3], Bl[r][rk+3]);
    }
    __syncthreads();

    const int NT = CDIM / 16;
    for (int kt = 0; kt < NT; kt++) {
        if (kt + 1 < NT) {
            const int k0 = (kt + 1) << 4;
            #pragma unroll
            for (int j = 0; j < 2; j++) {
                int ra = min(bm + rr + 64 * j, LTOK - 1);
                int rb = min(bn + rr + 64 * j, LTOK - 1);
                pa[j] = *(const float4*)(A + (size_t)ra * CDIM + k0 + rk);
                pb[j] = *(const float4*)(B + (size_t)rb * CDIM + k0 + rk);
            }
        }

        #pragma unroll
        for (int ks = 0; ks < 16; ks += 8) {
            uint32_t ah[2][4], al[2][4];
            #pragma unroll
            for (int mt = 0; mt < 2; mt++) {
                int mrow = wm * 32 + mt * 16 + g;
                ah[mt][0] = Ah[mrow    ][ks + t4    ];
                ah[mt][1] = Ah[mrow + 8][ks + t4    ];
                ah[mt][2] = Ah[mrow    ][ks + t4 + 4];
                ah[mt][3] = Ah[mrow + 8][ks + t4 + 4];
                al[mt][0] = Al[mrow    ][ks + t4    ];
                al[mt][1] = Al[mrow + 8][ks + t4    ];
                al[mt][2] = Al[mrow    ][ks + t4 + 4];
                al[mt][3] = Al[mrow + 8][ks + t4 + 4];
            }
            uint32_t bh[8][2], bl[8][2];
            #pragma unroll
            for (int nt = 0; nt < 8; nt++) {
                int ncol = wn * 64 + nt * 8 + g;
                bh[nt][0] = Bh[ncol][ks + t4    ];
                bh[nt][1] = Bh[ncol][ks + t4 + 4];
                bl[nt][0] = Bl[ncol][ks + t4    ];
                bl[nt][1] = Bl[ncol][ks + t4 + 4];
            }
            #pragma unroll
            for (int mt = 0; mt < 2; mt++)
                #pragma unroll
                for (int nt = 0; nt < 8; nt++) {
                    MMA_TF32(acc[mt][nt], ah[mt][0], ah[mt][1], ah[mt][2], ah[mt][3],
                             bl[nt][0], bl[nt][1]);
                    MMA_TF32(acc[mt][nt], al[mt][0], al[mt][1], al[mt][2], al[mt][3],
                             bh[nt][0], bh[nt][1]);
                    MMA_TF32(acc[mt][nt], ah[mt][0], ah[mt][1], ah[mt][2], ah[mt][3],
                             bh[nt][0], bh[nt][1]);
                }
        }
        __syncthreads();

        if (kt + 1 < NT) {
            #pragma unroll
            for (int j = 0; j < 2; j++) {
                int r = rr + 64 * j;
                split2(pa[j].x, Ah[r][rk+0], Al[r][rk+0]);
                split2(pa[j].y, Ah[r][rk+1], Al[r][rk+1]);
                split2(pa[j].z, Ah[r][rk+2], Al[r][rk+2]);
                split2(pa[j].w, Ah[r][rk+3], Al[r][rk+3]);
                split2(pb[j].x, Bh[r][rk+0], Bl[r][rk+0]);
                split2(pb[j].y, Bh[r][rk+1], Bl[r][rk+1]);
                split2(pb[j].z, Bh[r][rk+2], Bl[r][rk+2]);
                split2(pb[j].w, Bh[r][rk+3], Bl[r][rk+3]);
            }
            __syncthreads();
        }
    }

    float* Cmir = SYM ? C : CT;
    const bool offdiag = !SYM || (blockIdx.y != blockIdx.x);
    #pragma unroll
    for (int mt = 0; mt < 2; mt++) {
        #pragma unroll
        for (int nt = 0; nt < 8; nt++) {
            int row0 = bm + wm * 32 + mt * 16 + g;
            int col  = bn + wn * 64 + nt * 8 + 2 * t4;
            float v0 = acc[mt][nt][0] * scale, v1 = acc[mt][nt][1] * scale;
            float v2 = acc[mt][nt][2] * scale, v3 = acc[mt][nt][3] * scale;
            if (col < LTOK) {
                if (row0 < LTOK)
                    *(float2*)(C + (size_t)row0 * LTOK + col) = make_float2(v0, v1);
                if (row0 + 8 < LTOK)
                    *(float2*)(C + (size_t)(row0 + 8) * LTOK + col) = make_float2(v2, v3);
            }
            if (offdiag || !SYM) {
                if (row0 < LTOK) {
                    if (col < LTOK)     Cmir[(size_t)col * LTOK + row0]       = v0;
                    if (col + 1 < LTOK) Cmir[(size_t)(col + 1) * LTOK + row0] = v1;
                }
                if (row0 + 8 < LTOK) {
                    if (col < LTOK)     Cmir[(size_t)col * LTOK + row0 + 8]       = v2;
                    if (col + 1 < LTOK) Cmir[(size_t)(col + 1) * LTOK + row0 + 8] = v3;
                }
            } else if (SYM) {
                if (row0 < LTOK) {
                    if (col < LTOK)     C[(size_t)col * LTOK + row0]       = v0;
                    if (col + 1 < LTOK) C[(size_t)(col + 1) * LTOK + row0] = v1;
                }
                if (row0 + 8 < LTOK) {
                    if (col < LTOK)     C[(size_t)col * LTOK + row0 + 8]       = v2;
                    if (col + 1 < LTOK) C[(size_t)(col + 1) * LTOK + row0 + 8] = v3;
                }
            }
        }
    }
}

// ====== tf32 GEMM, 128x128 tile (KV stacked) — single-sync double buffer ===
template <int ACT, int STACKB>
__global__ void __launch_bounds__(256, 2)
gemm128(const float* __restrict__ A, const float* __restrict__ B,
        float* __restrict__ C, int M, int N, int Kd)
{
    __shared__ uint32_t As[2][128][20];
    __shared__ uint32_t Bs[2][16][136];

    const int tid  = threadIdx.x;
    const int lane = tid & 31;
    const int warp = tid >> 5;
    const int wm   = warp & 3;
    const int wn   = warp >> 2;
    const int bm   = blockIdx.y * 128;
    const int bn   = blockIdx.x * 128;
    const int g  = lane >> 2;
    const int t4 = lane & 3;

    float acc[2][8][4];
    #pragma unroll
    for (int mt = 0; mt < 2; mt++)
        #pragma unroll
        for (int nt = 0; nt < 8; nt++)
            #pragma unroll
            for (int r = 0; r < 4; r++) acc[mt][nt][r] = 0.f;

    const int ar = tid >> 2;
    const int ak = (tid & 3) * 4;
    const int brow = tid >> 5;
    const int bcol = (tid & 31) * 4;

    const float* bptr;
    size_t bstride;
    if (STACKB) {
        int ncol = bn + bcol;
        bptr = B + (size_t)(ncol >> 8) * (CDIM * CDIM) + (ncol & 255);
        bstride = CDIM;
    } else {
        bptr = B + bn + bcol;
        bstride = (size_t)N;
    }

    const int NT = Kd >> 4;
    float4 pa[2], pb[2];

    #pragma unroll
    for (int j = 0; j < 2; j++) {
        pa[j] = *(const float4*)(A + (size_t)(bm + ar + 64 * j) * Kd + ak);
        pb[j] = *(const float4*)(bptr + (size_t)(brow + 8 * j) * bstride);
    }
    #pragma unroll
    for (int j = 0; j < 2; j++) {
        As[0][ar + 64 * j][ak + 0] = f2tf(pa[j].x);
        As[0][ar + 64 * j][ak + 1] = f2tf(pa[j].y);
        As[0][ar + 64 * j][ak + 2] = f2tf(pa[j].z);
        As[0][ar + 64 * j][ak + 3] = f2tf(pa[j].w);
        Bs[0][brow + 8 * j][bcol + 0] = f2tf(pb[j].x);
        Bs[0][brow + 8 * j][bcol + 1] = f2tf(pb[j].y);
        Bs[0][brow + 8 * j][bcol + 2] = f2tf(pb[j].z);
        Bs[0][brow + 8 * j][bcol + 3] = f2tf(pb[j].w);
    }
    __syncthreads();

    int buf = 0;
    for (int kt = 0; kt < NT; kt++) {
        if (kt + 1 < NT) {
            const int k0 = (kt + 1) << 4;
            #pragma unroll
            for (int j = 0; j < 2; j++) {
                pa[j] = *(const float4*)(A + (size_t)(bm + ar + 64 * j) * Kd + k0 + ak);
                pb[j] = *(const float4*)(bptr + (size_t)(k0 + brow + 8 * j) * bstride);
            }
        }

        #pragma unroll
        for (int ks = 0; ks < 16; ks += 8) {
            uint32_t af[2][4];
            #pragma unroll
            for (int mt = 0; mt < 2; mt++) {
                int mrow = wm * 32 + mt * 16 + g;
                af[mt][0] = As[buf][mrow    ][ks + t4    ];
                af[mt][1] = As[buf][mrow + 8][ks + t4    ];
                af[mt][2] = As[buf][mrow    ][ks + t4 + 4];
                af[mt][3] = As[buf][mrow + 8][ks + t4 + 4];
            }
            uint32_t bf[8][2];
            #pragma unroll
            for (int nt = 0; nt < 8; nt++) {
                int ncol = wn * 64 + nt * 8 + g;
                bf[nt][0] = Bs[buf][ks + t4    ][ncol];
                bf[nt][1] = Bs[buf][ks + t4 + 4][ncol];
            }
            #pragma unroll
            for (int mt = 0; mt < 2; mt++)
                #pragma unroll
                for (int nt = 0; nt < 8; nt++)
                    MMA_TF32(acc[mt][nt], af[mt][0], af[mt][1], af[mt][2], af[mt][3],
                             bf[nt][0], bf[nt][1]);
        }

        if (kt + 1 < NT) {
            int nb = buf ^ 1;
            #pragma unroll
            for (int j = 0; j < 2; j++) {
                As[nb][ar + 64 * j][ak + 0] = f2tf(pa[j].x);
                As[nb][ar + 64 * j][ak + 1] = f2tf(pa[j].y);
                As[nb][ar + 64 * j][ak + 2] = f2tf(pa[j].z);
                As[nb][ar + 64 * j][ak + 3] = f2tf(pa[j].w);
                Bs[nb][brow + 8 * j][bcol + 0] = f2tf(pb[j].x);
                Bs[nb][brow + 8 * j][bcol + 1] = f2tf(pb[j].y);
                Bs[nb][brow + 8 * j][bcol + 2] = f2tf(pb[j].z);
                Bs[nb][brow + 8 * j][bcol + 3] = f2tf(pb[j].w);
            }
            __syncthreads();
            buf = nb;
        }
    }

    #pragma unroll
    for (int mt = 0; mt < 2; mt++) {
        #pragma unroll
        for (int nt = 0; nt < 8; nt++) {
            int row = bm + wm * 32 + mt * 16 + g;
            int col = bn + wn * 64 + nt * 8 + 2 * t4;
            float v0 = acc[mt][nt][0], v1 = acc[mt][nt][1];
            float v2 = acc[mt][nt][2], v3 = acc[mt][nt][3];
            if (ACT == 1) {
                v0 = (v0 > 0.f) ? v0 + 1.f : expf(v0);
                v1 = (v1 > 0.f) ? v1 + 1.f : expf(v1);
                v2 = (v2 > 0.f) ? v2 + 1.f : expf(v2);
                v3 = (v3 > 0.f) ? v3 + 1.f : expf(v3);
            } else if (ACT == 2) {
                v0 = fmaxf(v0, 0.f); v1 = fmaxf(v1, 0.f);
                v2 = fmaxf(v2, 0.f); v3 = fmaxf(v3, 0.f);
            }
            if (STACKB) {
                size_t base = (size_t)(col >> 8) * ((size_t)TTOK * CDIM) + (col & 255);
                *(float2*)(C + base + (size_t)row * CDIM)       = make_float2(v0, v1);
                *(float2*)(C + base + (size_t)(row + 8) * CDIM) = make_float2(v2, v3);
            } else {
                *(float2*)(C + (size_t)row * N + col)       = make_float2(v0, v1);
                *(float2*)(C + (size_t)(row + 8) * N + col) = make_float2(v2, v3);
            }
        }
    }
}

// == tf32 GEMM, 128x64 tile — 3 CTAs/SM, single-sync (all loop GEMMs) =======
// Warp-tile 32x32: 16 LDS32 per 8 MMAs (ratio 0.5, best in family).
// 3 CTAs/SM -> 444 slots: N=256 launches (300 CTAs) run in ONE wave;
// W1 (600 CTAs) at 1.35 waves. smem 29.7KB x3 = 89KB; ~76 live regs < 85 cap.
template <int ACT>
__global__ void __launch_bounds__(256, 3)
gemm64(const float* __restrict__ A, const float* __restrict__ B,
       float* __restrict__ C, int M, int N, int Kd)
{
    __shared__ uint32_t As[2][128][20];
    __shared__ uint32_t Bs[2][16][72];

    const int tid  = threadIdx.x;
    const int lane = tid & 31;
    const int warp = tid >> 5;
    const int wm   = warp & 3;
    const int wn   = warp >> 2;
    const int bm   = blockIdx.y * 128;
    const int bn   = blockIdx.x * 64;
    const int g  = lane >> 2;
    const int t4 = lane & 3;

    float acc[2][4][4];
    #pragma unroll
    for (int mt = 0; mt < 2; mt++)
        #pragma unroll
        for (int nt = 0; nt < 4; nt++)
            #pragma unroll
            for (int r = 0; r < 4; r++) acc[mt][nt][r] = 0.f;

    const int ar = tid >> 2;
    const int ak = (tid & 3) * 4;
    const int brow = tid >> 4;
    const int bcol = (tid & 15) * 4;

    const int NT = Kd >> 4;
    float4 pa[2], pb;

    #pragma unroll
    for (int j = 0; j < 2; j++)
        pa[j] = *(const float4*)(A + (size_t)(bm + ar + 64 * j) * Kd + ak);
    pb = *(const float4*)(B + (size_t)brow * N + bn + bcol);
    #pragma unroll
    for (int j = 0; j < 2; j++) {
        As[0][ar + 64 * j][ak + 0] = f2tf(pa[j].x);
        As[0][ar + 64 * j][ak + 1] = f2tf(pa[j].y);
        As[0][ar + 64 * j][ak + 2] = f2tf(pa[j].z);
        As[0][ar + 64 * j][ak + 3] = f2tf(pa[j].w);
    }
    Bs[0][brow][bcol + 0] = f2tf(pb.x);
    Bs[0][brow][bcol + 1] = f2tf(pb.y);
    Bs[0][brow][bcol + 2] = f2tf(pb.z);
    Bs[0][brow][bcol + 3] = f2tf(pb.w);
    __syncthreads();

    int buf = 0;
    for (int kt = 0; kt < NT; kt++) {
        if (kt + 1 < NT) {
            const int k0 = (kt + 1) << 4;
            #pragma unroll
            for (int j = 0; j < 2; j++)
                pa[j] = *(const float4*)(A + (size_t)(bm + ar + 64 * j) * Kd + k0 + ak);
            pb = *(const float4*)(B + (size_t)(k0 + brow) * N + bn + bcol);
        }

        #pragma unroll
        for (int ks = 0; ks < 16; ks += 8) {
            uint32_t af[2][4];
            #pragma unroll
            for (int mt = 0; mt < 2; mt++) {
                int mrow = wm * 32 + mt * 16 + g;
                af[mt][0] = As[buf][mrow    ][ks + t4    ];
                af[mt][1] = As[buf][mrow + 8][ks + t4    ];
                af[mt][2] = As[buf][mrow    ][ks + t4 + 4];
                af[mt][3] = As[buf][mrow + 8][ks + t4 + 4];
            }
            uint32_t bf[4][2];
            #pragma unroll
            for (int nt = 0; nt < 4; nt++) {
                int ncol = wn * 32 + nt * 8 + g;
                bf[nt][0] = Bs[buf][ks + t4    ][ncol];
                bf[nt][1] = Bs[buf][ks + t4 + 4][ncol];
            }
            #pragma unroll
            for (int mt = 0; mt < 2; mt++)
                #pragma unroll
                for (int nt = 0; nt < 4; nt++)
                    MMA_TF32(acc[mt][nt], af[mt][0], af[mt][1], af[mt][2], af[mt][3],
                             bf[nt][0], bf[nt][1]);
        }

        if (kt + 1 < NT) {
            int nb = buf ^ 1;
            #pragma unroll
            for (int j = 0; j < 2; j++) {
                As[nb][ar + 64 * j][ak + 0] = f2tf(pa[j].x);
                As[nb][ar + 64 * j][ak + 1] = f2tf(pa[j].y);
                As[nb][ar + 64 * j][ak + 2] = f2tf(pa[j].z);
                As[nb][ar + 64 * j][ak + 3] = f2tf(pa[j].w);
            }
            Bs[nb][brow][bcol + 0] = f2tf(pb.x);
            Bs[nb][brow][bcol + 1] = f2tf(pb.y);
            Bs[nb][brow][bcol + 2] = f2tf(pb.z);
            Bs[nb][brow][bcol + 3] = f2tf(pb.w);
            __syncthreads();
            buf = nb;
        }
    }

    #pragma unroll
    for (int mt = 0; mt < 2; mt++) {
        #pragma unroll
        for (int nt = 0; nt < 4; nt++) {
            int row = bm + wm * 32 + mt * 16 + g;
            int col = bn + wn * 32 + nt * 8 + 2 * t4;
            float v0 = acc[mt][nt][0], v1 = acc[mt][nt][1];
            float v2 = acc[mt][nt][2], v3 = acc[mt][nt][3];
            if (ACT == 1) {
                v0 = (v0 > 0.f) ? v0 + 1.f : expf(v0);
                v1 = (v1 > 0.f) ? v1 + 1.f : expf(v1);
                v2 = (v2 > 0.f) ? v2 + 1.f : expf(v2);
                v3 = (v3 > 0.f) ? v3 + 1.f : expf(v3);
            } else if (ACT == 2) {
                v0 = fmaxf(v0, 0.f); v1 = fmaxf(v1, 0.f);
                v2 = fmaxf(v2, 0.f); v3 = fmaxf(v3, 0.f);
            }
            *(float2*)(C + (size_t)row * N + col)       = make_float2(v0, v1);
            *(float2*)(C + (size_t)(row + 8) * N + col) = make_float2(v2, v3);
        }
    }
}

// --------------- per-row logsumexp key offset (single pass) ----------------
__global__ void __launch_bounds__(256)
row_stats(const float* __restrict__ S, float* __restrict__ koff)
{
    const int row = blockIdx.x;
    const float* r = S + (size_t)row * LTOK;
    const int tid = threadIdx.x;
    __shared__ float sm[8], ss[8];

    float m = -1e30f, s = 0.f;
    for (int j = tid; j < LTOK; j += 256) {
        float x = r[j];
        if (x > m) { s = s * expf(m - x) + 1.f; m = x; }
        else       { s += expf(x - m); }
    }
    #pragma unroll
    for (int o = 16; o; o >>= 1) {
        float om = __shfl_down_sync(0xffffffffu, m, o);
        float os = __shfl_down_sync(0xffffffffu, s, o);
        float M = fmaxf(m, om);
        s = s * expf(m - M) + os * expf(om - M);
        m = M;
    }
    if ((tid & 31) == 0) { sm[tid >> 5] = m; ss[tid >> 5] = s; }
    __syncthreads();
    if (tid < 32) {
        float mm = (tid < 8) ? sm[tid] : -1e30f;
        float sv = (tid < 8) ? ss[tid] : 0.f;
        #pragma unroll
        for (int o = 4; o; o >>= 1) {
            float om = __shfl_down_sync(0xffffffffu, mm, o);
            float os = __shfl_down_sync(0xffffffffu, sv, o);
            float M = fmaxf(mm, om);
            sv = sv * expf(mm - M) + os * expf(om - M);
            mm = M;
        }
        if (tid == 0) koff[row] = mm + logf(sv);
    }
}

// -------------- top-16 per row (float4-vectorized scan) --------------------
__global__ void __launch_bounds__(256)
topk16(const float* __restrict__ S, const float* __restrict__ koff,
       int* __restrict__ out)
{
    const int row = blockIdx.x;
    const int tid = threadIdx.x;
    float lv[KSEL];
    int   li[KSEL];
    #pragma unroll
    for (int s = 0; s < KSEL; s++) { lv[s] = -1e30f; li[s] = 0x7fffffff; }

    const float4* r4 = (const float4*)(S + (size_t)row * LTOK);
    const float4* k4 = (const float4*)koff;
    const int NJ4 = LTOK / 4;
    for (int j4 = tid; j4 < NJ4; j4 += 256) {
        const float4 rv4 = r4[j4];
        const float4 kv4 = k4[j4];
        float cand[4] = {2.f * rv4.x - kv4.x, 2.f * rv4.y - kv4.y,
                         2.f * rv4.z - kv4.z, 2.f * rv4.w - kv4.w};
        #pragma unroll
        for (int c = 0; c < 4; c++) {
            float nv = cand[c];
            int ni = j4 * 4 + c;
            if (nv > lv[KSEL - 1] || (nv == lv[KSEL - 1] && ni < li[KSEL - 1])) {
                #pragma unroll
                for (int s = 0; s < KSEL; s++) {
                    bool better = (nv > lv[s]) || (nv == lv[s] && ni < li[s]);
                    if (better) {
                        float tv = lv[s]; int ti = li[s];
                        lv[s] = nv; li[s] = ni; nv = tv; ni = ti;
                    }
                }
            }
        }
    }

    __shared__ float tv[256 * KSEL];
    __shared__ int   ti[256 * KSEL];
    __shared__ float rv[256];
    __shared__ int   ri[256];
    __shared__ int   rt[256];
    #pragma unroll
    for (int s = 0; s < KSEL; s++) { tv[tid * KSEL + s] = lv[s]; ti[tid * KSEL + s] = li[s]; }
    __syncthreads();

    int hp = 0;
    for (int k = 0; k < KSEL; k++) {
        rv[tid] = (hp < KSEL) ? tv[tid * KSEL + hp] : -1e30f;
        ri[tid] = (hp < KSEL) ? ti[tid * KSEL + hp] : 0x7fffffff;
        rt[tid] = tid;
        __syncthreads();
        for (int o = 128; o; o >>= 1) {
            if (tid < o) {
                float ov = rv[tid + o]; int oi = ri[tid + o];
                if (ov > rv[tid] || (ov == rv[tid] && oi < ri[tid])) {
                    rv[tid] = ov; ri[tid] = oi; rt[tid] = rt[tid + o];
                }
            }
            __syncthreads();
        }
        if (tid == 0) out[row * KSEL + k] = ri[0];
        if (tid == rt[0]) hp++;
        __syncthreads();
    }
}

// ---- linear attention: warp per token, shfl-only, float4 (no smem/bars) ---
__global__ void __launch_bounds__(256)
attn_w(const float* __restrict__ Q,
       const float* __restrict__ KE, const float* __restrict__ V,
       const int* __restrict__ idxA, const int* __restrict__ idxB,
       int srcOffA, int srcOffB,
       float* __restrict__ out)
{
    const int warp = threadIdx.x >> 5, lane = threadIdx.x & 31;
    const int t = blockIdx.x * 8 + warp;
    const int side = (t >= LTOK);
    const int tl = side ? t - LTOK : t;
    const int* idx = side ? idxB : idxA;
    const int srcOff = side ? srcOffB : srcOffA;

    int myidx = 0;
    if (lane < KSEL) myidx = srcOff + idx[tl * KSEL + lane];

    const float4* Q4  = (const float4*)Q;
    const float4* KE4 = (const float4*)KE;
    const float4* V4  = (const float4*)V;

    const float4 q0 = Q4[(size_t)t * 64 + lane * 2];
    const float4 q1 = Q4[(size_t)t * 64 + lane * 2 + 1];

    float o0x=0.f,o0y=0.f,o0z=0.f,o0w=0.f, o1x=0.f,o1y=0.f,o1z=0.f,o1w=0.f;
    float zs = 1e-6f;

    #pragma unroll
    for (int s = 0; s < KSEL; s++) {
        const int src = __shfl_sync(0xffffffffu, myidx, s);
        const size_t base = (size_t)src * 64 + lane * 2;
        const float4 k0 = KE4[base];
        const float4 k1 = KE4[base + 1];
        float p = q0.x*k0.x + q0.y*k0.y + q0.z*k0.z + q0.w*k0.w
                + q1.x*k1.x + q1.y*k1.y + q1.z*k1.z + q1.w*k1.w;
        p += __shfl_down_sync(0xffffffffu, p, 2);
        p += __shfl_down_sync(0xffffffffu, p, 1);
        const float sc = __shfl_sync(0xffffffffu, p, lane & 28);
        zs += sc;
        const float4 v0 = V4[base];
        const float4 v1 = V4[base + 1];
        o0x += sc * v0.x; o0y += sc * v0.y; o0z += sc * v0.z; o0w += sc * v0.w;
        o1x += sc * v1.x; o1y += sc * v1.y; o1z += sc * v1.z; o1w += sc * v1.w;
    }

    const float inv = 1.f / zs;
    float4* O4 = (float4*)out;
    O4[(size_t)t * 64 + lane * 2]     = make_float4(o0x*inv, o0y*inv, o0z*inv, o0w*inv);
    O4[(size_t)t * 64 + lane * 2 + 1] = make_float4(o1x*inv, o1y*inv, o1z*inv, o1w*inv);
}

// -------------- warp-per-token LayerNorm kernels ---------------------------
__device__ __forceinline__ void warp_ln_stats(float4 v0, float4 v1,
                                              float& mu, float& rstd)
{
    float s  = v0.x + v0.y + v0.z + v0.w + v1.x + v1.y + v1.z + v1.w;
    float s2 = v0.x*v0.x + v0.y*v0.y + v0.z*v0.z + v0.w*v0.w
             + v1.x*v1.x + v1.y*v1.y + v1.z*v1.z + v1.w*v1.w;
    #pragma unroll
    for (int o = 16; o; o >>= 1) {
        s  += __shfl_xor_sync(0xffffffffu, s,  o);
        s2 += __shfl_xor_sync(0xffffffffu, s2, o);
    }
    mu = s * (1.f / CDIM);
    float var = s2 * (1.f / CDIM) - mu * mu;
    rstd = rsqrtf(var + 1e-5f);
}

__global__ void __launch_bounds__(256)
ln_cat_w(const float* __restrict__ X, const float* __restrict__ Msg,
         const float* __restrict__ gw, const float* __restrict__ bw,
         float* __restrict__ cat)
{
    const int warp = threadIdx.x >> 5, lane = threadIdx.x & 31;
    const int t = blockIdx.x * 8 + warp;
    const float4* mrow = (const float4*)(Msg + (size_t)t * CDIM);
    float4 v0 = mrow[lane], v1 = mrow[lane + 32];
    float mu, rstd;
    warp_ln_stats(v0, v1, mu, rstd);

    const float4* g4 = (const float4*)gw;
    const float4* b4 = (const float4*)bw;
    float4 ga = g4[lane], gb = g4[lane + 32];
    float4 ba = b4[lane], bb = b4[lane + 32];
    float4 o0, o1;
    o0.x = (v0.x - mu) * rstd * ga.x + ba.x;
    o0.y = (v0.y - mu) * rstd * ga.y + ba.y;
    o0.z = (v0.z - mu) * rstd * ga.z + ba.z;
    o0.w = (v0.w - mu) * rstd * ga.w + ba.w;
    o1.x = (v1.x - mu) * rstd * gb.x + bb.x;
    o1.y = (v1.y - mu) * rstd * gb.y + bb.y;
    o1.z = (v1.z - mu) * rstd * gb.z + bb.z;
    o1.w = (v1.w - mu) * rstd * gb.w + bb.w;

    const float4* xrow = (const float4*)(X + (size_t)t * CDIM);
    float4* crow = (float4*)(cat + (size_t)t * 2 * CDIM);
    crow[lane]      = xrow[lane];
    crow[lane + 32] = xrow[lane + 32];
    crow[lane + 64] = o0;
    crow[lane + 96] = o1;
}

__global__ void __launch_bounds__(256)
ln_res_w(const float* __restrict__ Y, const float* __restrict__ gw,
         const float* __restrict__ bw, float* __restrict__ X)
{
    const int warp = threadIdx.x >> 5, lane = threadIdx.x & 31;
    const int t = blockIdx.x * 8 + warp;
    const float4* yrow = (const float4*)(Y + (size_t)t * CDIM);
    float4 v0 = yrow[lane], v1 = yrow[lane + 32];
    float mu, rstd;
    warp_ln_stats(v0, v1, mu, rstd);

    const float4* g4 = (const float4*)gw;
    const float4* b4 = (const float4*)bw;
    float4 ga = g4[lane], gb = g4[lane + 32];
    float4 ba = b4[lane], bb = b4[lane + 32];

    float4* xrow = (float4*)(X + (size_t)t * CDIM);
    float4 x0 = xrow[lane], x1 = xrow[lane + 32];
    x0.x += (v0.x - mu) * rstd * ga.x + ba.x;
    x0.y += (v0.y - mu) * rstd * ga.y + ba.y;
    x0.z += (v0.z - mu) * rstd * ga.z + ba.z;
    x0.w += (v0.w - mu) * rstd * ga.w + ba.w;
    x1.x += (v1.x - mu) * rstd * gb.x + bb.x;
    x1.y += (v1.y - mu) * rstd * gb.y + bb.y;
    x1.z += (v1.z - mu) * rstd * gb.z + bb.z;
    x1.w += (v1.w - mu) * rstd * gb.w + bb.w;
    xrow[lane]      = x0;
    xrow[lane + 32] = x1;
}

__global__ void copy_f(const float* __restrict__ in, float* __restrict__ out, int n)
{
    int i = blockIdx.x * 256 + threadIdx.x;
    if (i < n) out[i] = in[i];
}

__global__ void copy2_f(const float* __restrict__ in, float* __restrict__ o1,
                        float* __restrict__ o2, int n)
{
    int i = blockIdx.x * 256 + threadIdx.x;
    if (i < n) { float v = in[i]; o1[i] = v; o2[i] = v; }
}

// ===========================================================================
extern "C" void kernel_launch(void* const* d_in, const int* in_sizes, int n_in,
                              void* d_out, int out_size)
{
    const float* feat0 = (const float*)d_in[0];
    const float* feat1 = (const float*)d_in[1];
    const float* Wq = (const float*)d_in[2];
    const float* Wk = (const float*)d_in[3];
    const float* Wv = (const float*)d_in[4];
    const float* Wm = (const float*)d_in[5];
    const float* W1 = (const float*)d_in[6];
    const float* W2 = (const float*)d_in[7];
    const float* g1 = (const float*)d_in[8];
    const float* b1 = (const float*)d_in[9];
    const float* g2 = (const float*)d_in[10];
    const float* b2 = (const float*)d_in[11];
    float* out = (float*)d_out;

    float *simA, *simB, *koff00, *koff11, *koffA, *koffB;
    int *idx00, *idx11, *idx01, *idx10;
    float *F, *X, *KEall, *Vall, *Qb, *attn, *msg, *cat, *h1, *y;
    cudaGetSymbolAddress((void**)&simA, g_simA);
    cudaGetSymbolAddress((void**)&simB, g_simB);
    cudaGetSymbolAddress((void**)&koff00, g_koff00);
    cudaGetSymbolAddress((void**)&koff11, g_koff11);
    cudaGetSymbolAddress((void**)&koffA, g_koffA);
    cudaGetSymbolAddress((void**)&koffB, g_koffB);
    cudaGetSymbolAddress((void**)&idx00, g_idx00);
    cudaGetSymbolAddress((void**)&idx11, g_idx11);
    cudaGetSymbolAddress((void**)&idx01, g_idx01);
    cudaGetSymbolAddress((void**)&idx10, g_idx10);
    cudaGetSymbolAddress((void**)&F, g_F);
    cudaGetSymbolAddress((void**)&X, g_X);
    cudaGetSymbolAddress((void**)&KEall, g_KEall);
    cudaGetSymbolAddress((void**)&Vall, g_Vall);
    cudaGetSymbolAddress((void**)&Qb, g_Qb);
    cudaGetSymbolAddress((void**)&attn, g_attn);
    cudaGetSymbolAddress((void**)&msg, g_msg);
    cudaGetSymbolAddress((void**)&cat, g_cat);
    cudaGetSymbolAddress((void**)&h1, g_h1);
    cudaGetSymbolAddress((void**)&y, g_y);

    const dim3 simGrid((LTOK + 127) / 128, (LTOK + 127) / 128);
    const dim3 gKV(NLAYER * CDIM / 128, TTOK / 128);   // 16 x 75
    const dim3 n256(CDIM / 64, TTOK / 128);            // 4 x 75 = 300 CTAs (1 wave @ 3/SM)
    const dim3 n512(2 * CDIM / 64, TTOK / 128);        // 8 x 75 = 600 CTAs (1.35 waves)

    // ---- stage 1: sim matrices (3-term split-tf32), stats, top-K ----
    gemm_nt_tc<1><<<simGrid, 256>>>(feat0, feat0, simA, simA, SIM_SCALE);
    row_stats<<<LTOK, 256>>>(simA, koff00);
    topk16<<<LTOK, 256>>>(simA, koff00, idx00);

    gemm_nt_tc<1><<<simGrid, 256>>>(feat1, feat1, simA, simA, SIM_SCALE);
    row_stats<<<LTOK, 256>>>(simA, koff11);
    topk16<<<LTOK, 256>>>(simA, koff11, idx11);

    gemm_nt_tc<0><<<simGrid, 256>>>(feat0, feat1, simA, simB, SIM_SCALE);
    row_stats<<<LTOK, 256>>>(simA, koffA);
    row_stats<<<LTOK, 256>>>(simB, koffB);
    topk16<<<LTOK, 256>>>(simA, koffB, idx01);
    topk16<<<LTOK, 256>>>(simB, koffA, idx10);

    // ---- stage 2: concat features, all-layer K/V tables (layer-major) ----
    copy2_f<<<(LTOK * CDIM + 255) / 256, 256>>>(feat0, F, X, LTOK * CDIM);
    copy2_f<<<(LTOK * CDIM + 255) / 256, 256>>>(feat1, F + (size_t)LTOK * CDIM,
                                                X + (size_t)LTOK * CDIM, LTOK * CDIM);
    gemm128<1, 1><<<gKV, 256>>>(F, Wk, KEall, TTOK, NLAYER * CDIM, CDIM);
    gemm128<0, 1><<<gKV, 256>>>(F, Wv, Vall,  TTOK, NLAYER * CDIM, CDIM);

    // ---- stage 3: 8 encoder layers, both sides batched ----
    for (int i = 0; i < NLAYER; i++) {
        const float* wq = Wq + (size_t)i * CDIM * CDIM;
        const float* wm = Wm + (size_t)i * CDIM * CDIM;
        const float* w1 = W1 + (size_t)i * 2 * CDIM * 2 * CDIM;
        const float* w2 = W2 + (size_t)i * 2 * CDIM * CDIM;
        const float* gg1 = g1 + (size_t)i * CDIM;
        const float* bb1 = b1 + (size_t)i * CDIM;
        const float* gg2 = g2 + (size_t)i * CDIM;
        const float* bb2 = b2 + (size_t)i * CDIM;
        const bool cross = (i & 1);

        const int* idxA = cross ? idx01 : idx00;
        const int* idxB = cross ? idx10 : idx11;
        const int srcOffA = cross ? LTOK : 0;
        const int srcOffB = cross ? 0 : LTOK;

        const float* KEl = KEall + (size_t)i * TTOK * CDIM;
        const float* Vl  = Vall  + (size_t)i * TTOK * CDIM;

        gemm64<1><<<n256, 256>>>(X, wq, Qb, TTOK, CDIM, CDIM);
        attn_w<<<TTOK / 8, 256>>>(Qb, KEl, Vl, idxA, idxB, srcOffA, srcOffB, attn);
        gemm64<0><<<n256, 256>>>(attn, wm, msg, TTOK, CDIM, CDIM);
        ln_cat_w<<<TTOK / 8, 256>>>(X, msg, gg1, bb1, cat);
        gemm64<2><<<n512, 256>>>(cat, w1, h1, TTOK, 2 * CDIM, 2 * CDIM);
        gemm64<0><<<n256, 256>>>(h1, w2, y, TTOK, CDIM, 2 * CDIM);
        ln_res_w<<<TTOK / 8, 256>>>(y, gg2, bb2, X);
    }

    // ---- stage 4: output ----
    copy_f<<<(TTOK * CDIM + 255) / 256, 256>>>(X, out, TTOK * CDIM);
}